// round 12
// baseline (speedup 1.0000x reference)
#include <cuda_runtime.h>
#include <cuda_fp16.h>
#include <math.h>

#define N_NODES 20000
#define N_GRAPH 64
#define NH 4
#define NC 64
#define NFIN 128
#define NHC 256
#define E_RAW 320000
#define E_TOT (E_RAW + N_NODES)
#define BN_EPS 1e-5f

// ---------------- scratch (device globals; zero-initialized at load) -------
static __device__ __align__(16) __half g_h1h[N_NODES * NHC];
static __device__ __align__(16) __half g_hmidh[N_NODES * NC];
static __device__ float g_skip[N_NODES * NC];
static __device__ float g_es[N_NODES * NH];
static __device__ float g_ed[N_NODES * NH];
static __device__ float g_acc[N_NODES * NC];
static __device__ float g_bnstats[4 * NC];           // kept zeroed between calls
static __device__ __align__(16) int g_cnt[N_NODES];  // kept zeroed between calls
static __device__ int   g_rowptr[N_NODES + 1];
static __device__ int   g_rank[E_TOT];
static __device__ int   g_csrc[E_TOT];
static __device__ int   g_histdone;                  // kept zeroed between calls

__device__ __forceinline__ float gelu_exact(float x) {
    return 0.5f * x * (1.f + erff(x * 0.70710678118654752440f));
}

__device__ __forceinline__ unsigned smem_u32(const void* p) {
    return (unsigned)__cvta_generic_to_shared(p);
}

__device__ __forceinline__ void ldm_x4(unsigned r[4], unsigned addr) {
    asm volatile("ldmatrix.sync.aligned.m8n8.x4.shared.b16 {%0,%1,%2,%3}, [%4];"
        : "=r"(r[0]), "=r"(r[1]), "=r"(r[2]), "=r"(r[3]) : "r"(addr));
}
__device__ __forceinline__ void ldm_x2t(unsigned r[2], unsigned addr) {
    asm volatile("ldmatrix.sync.aligned.m8n8.x2.trans.shared.b16 {%0,%1}, [%2];"
        : "=r"(r[0]), "=r"(r[1]) : "r"(addr));
}
__device__ __forceinline__ void mma16816(float c[4], const unsigned a[4], const unsigned b[2]) {
    asm volatile("mma.sync.aligned.m16n8k16.row.col.f32.f16.f16.f32 "
        "{%0,%1,%2,%3}, {%4,%5,%6,%7}, {%8,%9}, {%0,%1,%2,%3};"
        : "+f"(c[0]), "+f"(c[1]), "+f"(c[2]), "+f"(c[3])
        : "r"(a[0]), "r"(a[1]), "r"(a[2]), "r"(a[3]), "r"(b[0]), "r"(b[1]));
}

__device__ __forceinline__ uint4 pack8h(float4 fa, float4 fb) {
    __half2 h0 = __floats2half2_rn(fa.x, fa.y);
    __half2 h1 = __floats2half2_rn(fa.z, fa.w);
    __half2 h2 = __floats2half2_rn(fb.x, fb.y);
    __half2 h3 = __floats2half2_rn(fb.z, fb.w);
    return make_uint4(*(unsigned*)&h0, *(unsigned*)&h1, *(unsigned*)&h2, *(unsigned*)&h3);
}

// ===== hist + scan fused =====
__global__ void __launch_bounds__(1024) hist_scan_kernel(
    const int* __restrict__ ei, int E, int etot, int n, int nblocks)
{
    int t = threadIdx.x;
    for (int e = blockIdx.x * 1024 + t; e < etot; e += nblocks * 1024) {
        int d = (e < E) ? ei[E + e] : (e - E);
        g_rank[e] = atomicAdd(&g_cnt[d], 1);
    }
    __threadfence();
    __shared__ int isLast;
    if (t == 0) isLast = (atomicAdd(&g_histdone, 1) == nblocks - 1);
    __syncthreads();
    if (!isLast) return;
    if (t == 0) g_histdone = 0;

    const int PER = 20;
    int lane = t & 31, wid = t >> 5;
    int base = t * PER;
    int v[PER];
    if (base + PER <= n) {
        const int4* p = (const int4*)(g_cnt + base);
#pragma unroll
        for (int i = 0; i < 5; i++) {
            int4 q = p[i];
            v[4 * i] = q.x; v[4 * i + 1] = q.y; v[4 * i + 2] = q.z; v[4 * i + 3] = q.w;
        }
    } else {
#pragma unroll
        for (int i = 0; i < PER; i++) v[i] = (base + i < n) ? g_cnt[base + i] : 0;
    }
    int sum = 0;
#pragma unroll
    for (int i = 0; i < PER; i++) sum += v[i];
    int s = sum;
#pragma unroll
    for (int o = 1; o < 32; o <<= 1) {
        int x = __shfl_up_sync(0xffffffffu, s, o);
        if (lane >= o) s += x;
    }
    __shared__ int wp[32];
    if (lane == 31) wp[wid] = s;
    __syncthreads();
    if (wid == 0) {
        int orig = wp[lane];
        int ws = orig;
#pragma unroll
        for (int o = 1; o < 32; o <<= 1) {
            int x = __shfl_up_sync(0xffffffffu, ws, o);
            if (lane >= o) ws += x;
        }
        wp[lane] = ws - orig;
    }
    __syncthreads();
    int run = wp[wid] + s - sum;
#pragma unroll
    for (int i = 0; i < PER; i++) {
        if (base + i < n) g_rowptr[base + i] = run;
        run += v[i];
    }
    if (t == 1023) g_rowptr[n] = run;
}

// ========== HMMA GEMM body ==========
// AF32: A fp32 from Af (converted in loader).
// AFUSE: A tile computed as gelu(BN(g_acc)+g_skip+bskip) via sc64/sh64 smem
//        params; head-0 block also writes g_hmidh.
template <bool ATTN, bool AF32, bool AFUSE>
__device__ __forceinline__ void gemm_body(
    __half* As, __half* Bs,
    const __half* __restrict__ Ah, const float* __restrict__ Af,
    const float* __restrict__ Bf,
    float* __restrict__ Cf, __half* __restrict__ Ch,
    int n, int K, int ncols, int head, int bx,
    const float* __restrict__ asrc, const float* __restrict__ adst,
    const float* sc64, const float* sh64)
{
    const int tid = threadIdx.x;
    const int l = tid & 31, w = tid >> 5;
    const int wr = w >> 1, wc = w & 1;
    const int bm = bx * 128, bn = head * 64;

    float c[2][4][4];
#pragma unroll
    for (int mt = 0; mt < 2; mt++)
#pragma unroll
        for (int nt = 0; nt < 4; nt++)
#pragma unroll
            for (int j = 0; j < 4; j++) c[mt][nt][j] = 0.f;

    for (int k0 = 0; k0 < K; k0 += 64) {
        {
            int rlocal = tid >> 1;
            int row = bm + rlocal;
            int colh = (tid & 1) * 32;
            bool ok = row < n;
            if (AFUSE) {
                // K == 64 here; compute A = gelu(acc*sc + sh + skip)
                const float4* accp = (const float4*)(g_acc + (size_t)row * NC + colh);
                const float4* skp  = (const float4*)(g_skip + (size_t)row * NC + colh);
                uint4* dstp = (uint4*)(As + rlocal * 72 + colh);
                float4 z4 = make_float4(0.f, 0.f, 0.f, 0.f);
#pragma unroll
                for (int u = 0; u < 4; u++) {
                    float4 a0 = ok ? accp[2 * u]     : z4;
                    float4 a1 = ok ? accp[2 * u + 1] : z4;
                    float4 k0v = ok ? skp[2 * u]     : z4;
                    float4 k1v = ok ? skp[2 * u + 1] : z4;
                    float4 sc0 = *(const float4*)&sc64[colh + 8 * u];
                    float4 sc1 = *(const float4*)&sc64[colh + 8 * u + 4];
                    float4 sh0 = *(const float4*)&sh64[colh + 8 * u];
                    float4 sh1 = *(const float4*)&sh64[colh + 8 * u + 4];
                    float4 ra, rb;
                    ra.x = gelu_exact(a0.x * sc0.x + sh0.x + k0v.x);
                    ra.y = gelu_exact(a0.y * sc0.y + sh0.y + k0v.y);
                    ra.z = gelu_exact(a0.z * sc0.z + sh0.z + k0v.z);
                    ra.w = gelu_exact(a0.w * sc0.w + sh0.w + k0v.w);
                    rb.x = gelu_exact(a1.x * sc1.x + sh1.x + k1v.x);
                    rb.y = gelu_exact(a1.y * sc1.y + sh1.y + k1v.y);
                    rb.z = gelu_exact(a1.z * sc1.z + sh1.z + k1v.z);
                    rb.w = gelu_exact(a1.w * sc1.w + sh1.w + k1v.w);
                    uint4 pk = pack8h(ra, rb);
                    dstp[u] = pk;
                    if (head == 0 && ok)
                        ((uint4*)(g_hmidh + (size_t)row * NC + colh))[u] = pk;
                }
            } else if (AF32) {
                const float4* src = (const float4*)(Af + (size_t)row * K + k0 + colh);
                uint4* dstp = (uint4*)(As + rlocal * 72 + colh);
                float4 z4 = make_float4(0.f, 0.f, 0.f, 0.f);
#pragma unroll
                for (int u = 0; u < 4; u++) {
                    float4 fa = ok ? src[2 * u] : z4;
                    float4 fb = ok ? src[2 * u + 1] : z4;
                    dstp[u] = pack8h(fa, fb);
                }
            } else {
                uint4 z = make_uint4(0, 0, 0, 0);
                const uint4* src = (const uint4*)(Ah + (size_t)row * K + k0 + colh);
                uint4 v0 = ok ? src[0] : z;
                uint4 v1 = ok ? src[1] : z;
                uint4 v2 = ok ? src[2] : z;
                uint4 v3 = ok ? src[3] : z;
                uint4* dstp = (uint4*)(As + rlocal * 72 + colh);
                dstp[0] = v0; dstp[1] = v1; dstp[2] = v2; dstp[3] = v3;
            }
        }
        {
            int row = tid >> 2, colh = (tid & 3) * 16;
            const float4* src = (const float4*)(Bf + (size_t)(k0 + row) * ncols + bn + colh);
            uint4* dstp = (uint4*)(Bs + row * 72 + colh);
#pragma unroll
            for (int u = 0; u < 2; u++) {
                float4 fa = src[2 * u];
                float4 fb = src[2 * u + 1];
                dstp[u] = pack8h(fa, fb);
            }
        }
        __syncthreads();
#pragma unroll
        for (int kk = 0; kk < 4; kk++) {
            unsigned af[2][4];
#pragma unroll
            for (int mt = 0; mt < 2; mt++) {
                int rowA = wr * 32 + mt * 16 + (l & 15);
                int colA = kk * 16 + ((l >> 4) << 3);
                ldm_x4(af[mt], smem_u32(As + rowA * 72 + colA));
            }
            unsigned bf[4][2];
#pragma unroll
            for (int nt = 0; nt < 4; nt++) {
                int rowB = kk * 16 + (l & 15);
                int colB = wc * 32 + nt * 8;
                ldm_x2t(bf[nt], smem_u32(Bs + rowB * 72 + colB));
            }
#pragma unroll
            for (int mt = 0; mt < 2; mt++)
#pragma unroll
                for (int nt = 0; nt < 4; nt++)
                    mma16816(c[mt][nt], af[mt], bf[nt]);
        }
        __syncthreads();
    }

    if (ATTN) {
        float as8[8], ad8[8];
        int cb = wc * 32 + 2 * (l & 3);
#pragma unroll
        for (int nt = 0; nt < 4; nt++) {
            as8[2 * nt]     = asrc[bn + cb + nt * 8];
            as8[2 * nt + 1] = asrc[bn + cb + nt * 8 + 1];
            ad8[2 * nt]     = adst[bn + cb + nt * 8];
            ad8[2 * nt + 1] = adst[bn + cb + nt * 8 + 1];
        }
        float* Ses = (float*)As;
        float* Sed = Ses + 256;
#pragma unroll
        for (int mt = 0; mt < 2; mt++) {
            int r0 = bm + wr * 32 + mt * 16 + (l >> 2);
            int r1 = r0 + 8;
            float plo = 0.f, phi = 0.f, qlo = 0.f, qhi = 0.f;
#pragma unroll
            for (int nt = 0; nt < 4; nt++) {
                float c0 = c[mt][nt][0], c1 = c[mt][nt][1];
                float c2 = c[mt][nt][2], c3 = c[mt][nt][3];
                int col = bn + wc * 32 + nt * 8 + 2 * (l & 3);
                if (r0 < n) *(__half2*)&Ch[(size_t)r0 * ncols + col] = __floats2half2_rn(c0, c1);
                if (r1 < n) *(__half2*)&Ch[(size_t)r1 * ncols + col] = __floats2half2_rn(c2, c3);
                plo += c0 * as8[2 * nt] + c1 * as8[2 * nt + 1];
                phi += c2 * as8[2 * nt] + c3 * as8[2 * nt + 1];
                qlo += c0 * ad8[2 * nt] + c1 * ad8[2 * nt + 1];
                qhi += c2 * ad8[2 * nt] + c3 * ad8[2 * nt + 1];
            }
#pragma unroll
            for (int off = 1; off <= 2; off <<= 1) {
                plo += __shfl_xor_sync(0xffffffffu, plo, off);
                phi += __shfl_xor_sync(0xffffffffu, phi, off);
                qlo += __shfl_xor_sync(0xffffffffu, qlo, off);
                qhi += __shfl_xor_sync(0xffffffffu, qhi, off);
            }
            if ((l & 3) == 0) {
                int rr = wr * 32 + mt * 16 + (l >> 2);
                Ses[rr * 2 + wc] = plo;
                Ses[(rr + 8) * 2 + wc] = phi;
                Sed[rr * 2 + wc] = qlo;
                Sed[(rr + 8) * 2 + wc] = qhi;
            }
        }
        __syncthreads();
        if (tid < 128) {
            int row = bm + tid;
            if (row < n) {
                g_es[row * 4 + head] = Ses[tid * 2] + Ses[tid * 2 + 1];
                g_ed[row * 4 + head] = Sed[tid * 2] + Sed[tid * 2 + 1];
            }
        }
    } else {
#pragma unroll
        for (int mt = 0; mt < 2; mt++) {
            int r0 = bm + wr * 32 + mt * 16 + (l >> 2);
            int r1 = r0 + 8;
#pragma unroll
            for (int nt = 0; nt < 4; nt++) {
                int col = bn + wc * 32 + nt * 8 + 2 * (l & 3);
                if (r0 < n) *(float2*)&Cf[(size_t)r0 * ncols + col] =
                    make_float2(c[mt][nt][0], c[mt][nt][1]);
                if (r1 < n) *(float2*)&Cf[(size_t)r1 * ncols + col] =
                    make_float2(c[mt][nt][2], c[mt][nt][3]);
            }
        }
    }
}

// == mega: y=0 placement | y=1..4 W1-GEMM head (+attn) | y=5 skip GEMM ==
__global__ void __launch_bounds__(256) mega1_kernel(
    const float* __restrict__ x, const float* __restrict__ W1,
    const float* __restrict__ Wskip,
    const float* __restrict__ asrc, const float* __restrict__ adst,
    const int* __restrict__ ei, int n, int E, int etot)
{
    __shared__ __half As[128 * 72];
    __shared__ __half Bs[64 * 72];
    int y = blockIdx.y;
    if (y == 0) {
        for (int e = blockIdx.x * blockDim.x + threadIdx.x; e < etot;
             e += gridDim.x * blockDim.x) {
            int s, d;
            if (e < E) { s = __ldg(ei + e); d = __ldg(ei + E + e); }
            else       { s = e - E;         d = s; }
            int pos = g_rowptr[d] + g_rank[e];
            g_csrc[pos] = s;
        }
    } else if (y <= 4) {
        gemm_body<true, true, false>(As, Bs, nullptr, x, W1, nullptr, g_h1h,
                                     n, NFIN, NHC, y - 1, blockIdx.x, asrc, adst,
                                     nullptr, nullptr);
    } else {
        gemm_body<false, true, false>(As, Bs, nullptr, x, Wskip, g_skip, nullptr,
                                      n, NFIN, NC, 0, blockIdx.x, nullptr, nullptr,
                                      nullptr, nullptr);
    }
}

// ===== layer-2 GEMM with fused BN+skip+GELU A-loader (replaces fuse1) =====
__global__ void __launch_bounds__(256) hgemm2_fused_kernel(
    const float* __restrict__ Bf, int n,
    const float* __restrict__ asrc, const float* __restrict__ adst,
    const float* __restrict__ bskip,
    const float* __restrict__ gamma, const float* __restrict__ beta,
    const float* __restrict__ sums, const float* __restrict__ sumsq, float ninv)
{
    __shared__ __half As[128 * 72];
    __shared__ __half Bs[64 * 72];
    __shared__ float s_sc[NC], s_sh[NC];
    if (threadIdx.x < NC) {
        int c = threadIdx.x;
        float mu = sums[c] * ninv;
        float var = sumsq[c] * ninv - mu * mu;
        float sc = gamma[c] * rsqrtf(var + BN_EPS);
        s_sc[c] = sc;
        s_sh[c] = beta[c] - mu * sc + bskip[c];
    }
    __syncthreads();
    gemm_body<true, false, true>(As, Bs, nullptr, nullptr, Bf, nullptr, g_h1h,
                                 n, NC, NHC, blockIdx.y, blockIdx.x, asrc, adst,
                                 s_sc, s_sh);
}

// == fused softmax + gather + BN-stats: warp/node, cross-batch sw pipeline ===
__global__ void __launch_bounds__(256) aggregate_kernel(
    int n, float* __restrict__ sums, float* __restrict__ sumsq)
{
    __shared__ float bsum[NC], bsq[NC];
    const int tid = threadIdx.x;
    if (tid < NC) { bsum[tid] = 0.f; bsq[tid] = 0.f; }
    __syncthreads();

    int w = (blockIdx.x * blockDim.x + tid) >> 5;
    int lane = tid & 31;
    const int h = lane >> 3;
    const int cb = (lane & 7) * 8;
    float a[8] = {0.f, 0.f, 0.f, 0.f, 0.f, 0.f, 0.f, 0.f};
    bool active = (w < n);

    if (active) {
        int beg = g_rowptr[w], end = g_rowptr[w + 1];
        float edv = g_ed[w * 4 + h];
        float s = 0.f;
        const __half* hb = g_h1h + h * 64 + cb;
        float a0 = 0.f, a1 = 0.f, a2 = 0.f, a3 = 0.f;
        float a4 = 0.f, a5 = 0.f, a6 = 0.f, a7 = 0.f;

        int nfull = (end - beg) & ~7;
        int pend = beg + nfull;
        int pos = beg;
        if (nfull > 0) {
            int sv[8];
#pragma unroll
            for (int q = 0; q < 8; q++) sv[q] = g_csrc[pos + q];
            while (true) {
                float ev[8]; uint4 vv[8];
#pragma unroll
                for (int q = 0; q < 8; q++) {
                    ev[q] = g_es[sv[q] * 4 + h] + edv;
                    vv[q] = *(const uint4*)(hb + (size_t)sv[q] * NHC);
                }
                pos += 8;
                bool more = pos < pend;
                int nx[8];
                if (more) {
#pragma unroll
                    for (int q = 0; q < 8; q++) nx[q] = g_csrc[pos + q];
                }
#pragma unroll
                for (int q = 0; q < 8; q++) {
                    float e = ev[q];
                    e = e > 0.f ? e : 0.2f * e;
                    float p = __expf(e);
                    s += p;
                    float2 f0 = __half22float2(*(__half2*)&vv[q].x);
                    float2 f1 = __half22float2(*(__half2*)&vv[q].y);
                    float2 f2 = __half22float2(*(__half2*)&vv[q].z);
                    float2 f3 = __half22float2(*(__half2*)&vv[q].w);
                    a0 += p * f0.x; a1 += p * f0.y; a2 += p * f1.x; a3 += p * f1.y;
                    a4 += p * f2.x; a5 += p * f2.y; a6 += p * f3.x; a7 += p * f3.y;
                }
                if (!more) break;
#pragma unroll
                for (int q = 0; q < 8; q++) sv[q] = nx[q];
            }
        }
        for (; pos < end; pos++) {
            int s0 = g_csrc[pos];
            float e0 = g_es[s0 * 4 + h] + edv;
            uint4 v0 = *(const uint4*)(hb + (size_t)s0 * NHC);
            e0 = e0 > 0.f ? e0 : 0.2f * e0;
            float p0 = __expf(e0);
            s += p0;
            float2 f0 = __half22float2(*(__half2*)&v0.x);
            float2 f1 = __half22float2(*(__half2*)&v0.y);
            float2 f2 = __half22float2(*(__half2*)&v0.z);
            float2 f3 = __half22float2(*(__half2*)&v0.w);
            a0 += p0 * f0.x; a1 += p0 * f0.y; a2 += p0 * f1.x; a3 += p0 * f1.y;
            a4 += p0 * f2.x; a5 += p0 * f2.y; a6 += p0 * f3.x; a7 += p0 * f3.y;
        }
        float inv = 0.25f / (s + 1e-16f);
        a[0] = a0 * inv; a[1] = a1 * inv; a[2] = a2 * inv; a[3] = a3 * inv;
        a[4] = a4 * inv; a[5] = a5 * inv; a[6] = a6 * inv; a[7] = a7 * inv;
    }
#pragma unroll
    for (int j = 0; j < 8; j++) {
        a[j] += __shfl_xor_sync(0xffffffffu, a[j], 8);
        a[j] += __shfl_xor_sync(0xffffffffu, a[j], 16);
    }
    if (active && lane < 8) {
        *(float4*)&g_acc[w * NC + lane * 8]     = make_float4(a[0], a[1], a[2], a[3]);
        *(float4*)&g_acc[w * NC + lane * 8 + 4] = make_float4(a[4], a[5], a[6], a[7]);
#pragma unroll
        for (int j = 0; j < 8; j++) {
            atomicAdd(&bsum[lane * 8 + j], a[j]);
            atomicAdd(&bsq[lane * 8 + j], a[j] * a[j]);
        }
    }
    __syncthreads();
    if (tid < NC) {
        atomicAdd(&sums[tid], bsum[tid]);
        atomicAdd(&sumsq[tid], bsq[tid]);
    }
}

// ===== fused epilogue 2 + pool; tail re-zeros cnt & stats for next call =====
__device__ __forceinline__ int lower_bound_dev(const int* arr, int n, int target) {
    int lo = 0, hi = n;
    while (lo < hi) {
        int mid = (lo + hi) >> 1;
        if (arr[mid] < target) lo = mid + 1; else hi = mid;
    }
    return lo;
}

__global__ void fuse2_pool_kernel(const int* __restrict__ batch,
                                  const float* __restrict__ gamma,
                                  const float* __restrict__ beta,
                                  const float* __restrict__ sums,
                                  const float* __restrict__ sumsq,
                                  float ninv,
                                  float* __restrict__ out, int n)
{
    int g = blockIdx.x;
    __shared__ int bounds[2];
    if (threadIdx.x < 2)
        bounds[threadIdx.x] = lower_bound_dev(batch, n, g + threadIdx.x);
    __syncthreads();
    int lo = bounds[0], hi = bounds[1];
    int c = threadIdx.x & 63, rq = threadIdx.x >> 6;
    float mu = sums[c] * ninv;
    float var = sumsq[c] * ninv - mu * mu;
    float sc = gamma[c] * rsqrtf(var + BN_EPS);
    float sh = beta[c] - mu * sc;
    float s = 0.f;
    for (int node = lo + rq; node < hi; node += 4) {
        float res = __half2float(g_hmidh[node * NC + c]);
        float x = g_acc[node * NC + c] * sc + sh + res;
        s += gelu_exact(x);
    }
    __shared__ float red[256];
    red[threadIdx.x] = s;
    __syncthreads();
    if (threadIdx.x < 64) {
        float tot = red[c] + red[c + 64] + red[c + 128] + red[c + 192];
        out[g * NC + c] = tot / fmaxf((float)(hi - lo), 1.f);
    }
    for (int i = blockIdx.x * blockDim.x + threadIdx.x; i < n;
         i += gridDim.x * blockDim.x)
        g_cnt[i] = 0;
    if (blockIdx.x == 0 && threadIdx.x < 4 * NC)
        g_bnstats[threadIdx.x] = 0.f;
}

// ================= launch =================
extern "C" void kernel_launch(void* const* d_in, const int* in_sizes, int n_in,
                              void* d_out, int out_size) {
    const float* x      = (const float*)d_in[0];
    const float* W1     = (const float*)d_in[1];
    const float* a_src1 = (const float*)d_in[2];
    const float* a_dst1 = (const float*)d_in[3];
    const float* Wskip  = (const float*)d_in[5];
    const float* bskip  = (const float*)d_in[6];
    const float* g1     = (const float*)d_in[7];
    const float* be1    = (const float*)d_in[8];
    const float* W2     = (const float*)d_in[9];
    const float* a_src2 = (const float*)d_in[10];
    const float* a_dst2 = (const float*)d_in[11];
    const float* g2     = (const float*)d_in[13];
    const float* be2    = (const float*)d_in[14];
    const int*   ei     = (const int*)d_in[15];
    const int*   batch  = (const int*)d_in[16];
    float* out = (float*)d_out;

    int n = in_sizes[0] / NFIN;
    int E = in_sizes[15] / 2;
    int etot = E + n;
    float ninv = 1.f / (float)n;

    float* p_stats;
    cudaGetSymbolAddress((void**)&p_stats, g_bnstats);
    float* p_sums0  = p_stats;
    float* p_sumsq0 = p_stats + NC;
    float* p_sums1  = p_stats + 2 * NC;
    float* p_sumsq1 = p_stats + 3 * NC;

    int gx = (n + 127) / 128;
    int ab = (n * 32 + 255) / 256;
    int hb = (etot + 2047) / 2048;

    hist_scan_kernel<<<hb, 1024>>>(ei, E, etot, n, hb);

    mega1_kernel<<<dim3(gx, 6), 256>>>(x, W1, Wskip, a_src1, a_dst1, ei, n, E, etot);

    aggregate_kernel<<<ab, 256>>>(n, p_sums0, p_sumsq0);

    // layer-2 GEMM with BN+skip+GELU fused into the A-loader (head 0 writes hmidh)
    hgemm2_fused_kernel<<<dim3(gx, 4), 256>>>(W2, n, a_src2, a_dst2,
                                              bskip, g1, be1, p_sums0, p_sumsq0, ninv);

    aggregate_kernel<<<ab, 256>>>(n, p_sums1, p_sumsq1);
    fuse2_pool_kernel<<<N_GRAPH, 256>>>(batch, g2, be2, p_sums1, p_sumsq1, ninv, out, n);
}

// round 13
// speedup vs baseline: 1.0575x; 1.0575x over previous
#include <cuda_runtime.h>
#include <cuda_fp16.h>
#include <math.h>

#define N_NODES 20000
#define N_GRAPH 64
#define NH 4
#define NC 64
#define NFIN 128
#define NHC 256
#define E_RAW 320000
#define E_TOT (E_RAW + N_NODES)
#define BN_EPS 1e-5f

// ---------------- scratch (device globals; zero-initialized at load) -------
static __device__ __align__(16) __half g_h1h[N_NODES * NHC];
static __device__ __align__(16) __half g_hmidh[N_NODES * NC];
static __device__ float g_skip[N_NODES * NC];
static __device__ float g_es[N_NODES * NH];
static __device__ float g_ed[N_NODES * NH];
static __device__ float g_acc[N_NODES * NC];
static __device__ float g_bnstats[4 * NC];           // kept zeroed between calls
static __device__ __align__(16) int g_cnt[N_NODES];  // kept zeroed between calls
static __device__ int   g_rowptr[N_NODES + 1];
static __device__ int   g_rank[E_TOT];
static __device__ int   g_csrc[E_TOT];
static __device__ int   g_histdone;                  // kept zeroed between calls

__device__ __forceinline__ float gelu_exact(float x) {
    return 0.5f * x * (1.f + erff(x * 0.70710678118654752440f));
}

__device__ __forceinline__ unsigned smem_u32(const void* p) {
    return (unsigned)__cvta_generic_to_shared(p);
}

__device__ __forceinline__ void ldm_x4(unsigned r[4], unsigned addr) {
    asm volatile("ldmatrix.sync.aligned.m8n8.x4.shared.b16 {%0,%1,%2,%3}, [%4];"
        : "=r"(r[0]), "=r"(r[1]), "=r"(r[2]), "=r"(r[3]) : "r"(addr));
}
__device__ __forceinline__ void ldm_x2t(unsigned r[2], unsigned addr) {
    asm volatile("ldmatrix.sync.aligned.m8n8.x2.trans.shared.b16 {%0,%1}, [%2];"
        : "=r"(r[0]), "=r"(r[1]) : "r"(addr));
}
__device__ __forceinline__ void mma16816(float c[4], const unsigned a[4], const unsigned b[2]) {
    asm volatile("mma.sync.aligned.m16n8k16.row.col.f32.f16.f16.f32 "
        "{%0,%1,%2,%3}, {%4,%5,%6,%7}, {%8,%9}, {%0,%1,%2,%3};"
        : "+f"(c[0]), "+f"(c[1]), "+f"(c[2]), "+f"(c[3])
        : "r"(a[0]), "r"(a[1]), "r"(a[2]), "r"(a[3]), "r"(b[0]), "r"(b[1]));
}

__device__ __forceinline__ uint4 pack8h(float4 fa, float4 fb) {
    __half2 h0 = __floats2half2_rn(fa.x, fa.y);
    __half2 h1 = __floats2half2_rn(fa.z, fa.w);
    __half2 h2 = __floats2half2_rn(fb.x, fb.y);
    __half2 h3 = __floats2half2_rn(fb.z, fb.w);
    return make_uint4(*(unsigned*)&h0, *(unsigned*)&h1, *(unsigned*)&h2, *(unsigned*)&h3);
}

// ===== hist + scan fused =====
__global__ void __launch_bounds__(1024) hist_scan_kernel(
    const int* __restrict__ ei, int E, int etot, int n, int nblocks)
{
    int t = threadIdx.x;
    for (int e = blockIdx.x * 1024 + t; e < etot; e += nblocks * 1024) {
        int d = (e < E) ? ei[E + e] : (e - E);
        g_rank[e] = atomicAdd(&g_cnt[d], 1);
    }
    __threadfence();
    __shared__ int isLast;
    if (t == 0) isLast = (atomicAdd(&g_histdone, 1) == nblocks - 1);
    __syncthreads();
    if (!isLast) return;
    if (t == 0) g_histdone = 0;

    const int PER = 20;
    int lane = t & 31, wid = t >> 5;
    int base = t * PER;
    int v[PER];
    if (base + PER <= n) {
        const int4* p = (const int4*)(g_cnt + base);
#pragma unroll
        for (int i = 0; i < 5; i++) {
            int4 q = p[i];
            v[4 * i] = q.x; v[4 * i + 1] = q.y; v[4 * i + 2] = q.z; v[4 * i + 3] = q.w;
        }
    } else {
#pragma unroll
        for (int i = 0; i < PER; i++) v[i] = (base + i < n) ? g_cnt[base + i] : 0;
    }
    int sum = 0;
#pragma unroll
    for (int i = 0; i < PER; i++) sum += v[i];
    int s = sum;
#pragma unroll
    for (int o = 1; o < 32; o <<= 1) {
        int x = __shfl_up_sync(0xffffffffu, s, o);
        if (lane >= o) s += x;
    }
    __shared__ int wp[32];
    if (lane == 31) wp[wid] = s;
    __syncthreads();
    if (wid == 0) {
        int orig = wp[lane];
        int ws = orig;
#pragma unroll
        for (int o = 1; o < 32; o <<= 1) {
            int x = __shfl_up_sync(0xffffffffu, ws, o);
            if (lane >= o) ws += x;
        }
        wp[lane] = ws - orig;
    }
    __syncthreads();
    int run = wp[wid] + s - sum;
#pragma unroll
    for (int i = 0; i < PER; i++) {
        if (base + i < n) g_rowptr[base + i] = run;
        run += v[i];
    }
    if (t == 1023) g_rowptr[n] = run;
}

// ========== HMMA GEMM body (two-stage K=64 staging; STS.128 tile stores) ====
template <bool ATTN, bool AF32>
__device__ __forceinline__ void gemm_body(
    __half* As, __half* Bs,
    const __half* __restrict__ Ah, const float* __restrict__ Af,
    const float* __restrict__ Bf,
    float* __restrict__ Cf, __half* __restrict__ Ch,
    int n, int K, int ncols, int head, int bx,
    const float* __restrict__ asrc, const float* __restrict__ adst)
{
    const int tid = threadIdx.x;
    const int l = tid & 31, w = tid >> 5;
    const int wr = w >> 1, wc = w & 1;
    const int bm = bx * 128, bn = head * 64;

    float c[2][4][4];
#pragma unroll
    for (int mt = 0; mt < 2; mt++)
#pragma unroll
        for (int nt = 0; nt < 4; nt++)
#pragma unroll
            for (int j = 0; j < 4; j++) c[mt][nt][j] = 0.f;

    for (int k0 = 0; k0 < K; k0 += 64) {
        {
            int rlocal = tid >> 1;
            int row = bm + rlocal;
            int colh = (tid & 1) * 32;
            bool ok = row < n;
            if (AF32) {
                const float4* src = (const float4*)(Af + (size_t)row * K + k0 + colh);
                uint4* dstp = (uint4*)(As + rlocal * 72 + colh);
                float4 z4 = make_float4(0.f, 0.f, 0.f, 0.f);
#pragma unroll
                for (int u = 0; u < 4; u++) {
                    float4 fa = ok ? src[2 * u] : z4;
                    float4 fb = ok ? src[2 * u + 1] : z4;
                    dstp[u] = pack8h(fa, fb);
                }
            } else {
                uint4 z = make_uint4(0, 0, 0, 0);
                const uint4* src = (const uint4*)(Ah + (size_t)row * K + k0 + colh);
                uint4 v0 = ok ? src[0] : z;
                uint4 v1 = ok ? src[1] : z;
                uint4 v2 = ok ? src[2] : z;
                uint4 v3 = ok ? src[3] : z;
                uint4* dstp = (uint4*)(As + rlocal * 72 + colh);
                dstp[0] = v0; dstp[1] = v1; dstp[2] = v2; dstp[3] = v3;
            }
        }
        {
            int row = tid >> 2, colh = (tid & 3) * 16;
            const float4* src = (const float4*)(Bf + (size_t)(k0 + row) * ncols + bn + colh);
            uint4* dstp = (uint4*)(Bs + row * 72 + colh);
#pragma unroll
            for (int u = 0; u < 2; u++) {
                float4 fa = src[2 * u];
                float4 fb = src[2 * u + 1];
                dstp[u] = pack8h(fa, fb);
            }
        }
        __syncthreads();
#pragma unroll
        for (int kk = 0; kk < 4; kk++) {
            unsigned af[2][4];
#pragma unroll
            for (int mt = 0; mt < 2; mt++) {
                int rowA = wr * 32 + mt * 16 + (l & 15);
                int colA = kk * 16 + ((l >> 4) << 3);
                ldm_x4(af[mt], smem_u32(As + rowA * 72 + colA));
            }
            unsigned bf[4][2];
#pragma unroll
            for (int nt = 0; nt < 4; nt++) {
                int rowB = kk * 16 + (l & 15);
                int colB = wc * 32 + nt * 8;
                ldm_x2t(bf[nt], smem_u32(Bs + rowB * 72 + colB));
            }
#pragma unroll
            for (int mt = 0; mt < 2; mt++)
#pragma unroll
                for (int nt = 0; nt < 4; nt++)
                    mma16816(c[mt][nt], af[mt], bf[nt]);
        }
        __syncthreads();
    }

    if (ATTN) {
        float as8[8], ad8[8];
        int cb = wc * 32 + 2 * (l & 3);
#pragma unroll
        for (int nt = 0; nt < 4; nt++) {
            as8[2 * nt]     = asrc[bn + cb + nt * 8];
            as8[2 * nt + 1] = asrc[bn + cb + nt * 8 + 1];
            ad8[2 * nt]     = adst[bn + cb + nt * 8];
            ad8[2 * nt + 1] = adst[bn + cb + nt * 8 + 1];
        }
        float* Ses = (float*)As;
        float* Sed = Ses + 256;
#pragma unroll
        for (int mt = 0; mt < 2; mt++) {
            int r0 = bm + wr * 32 + mt * 16 + (l >> 2);
            int r1 = r0 + 8;
            float plo = 0.f, phi = 0.f, qlo = 0.f, qhi = 0.f;
#pragma unroll
            for (int nt = 0; nt < 4; nt++) {
                float c0 = c[mt][nt][0], c1 = c[mt][nt][1];
                float c2 = c[mt][nt][2], c3 = c[mt][nt][3];
                int col = bn + wc * 32 + nt * 8 + 2 * (l & 3);
                if (r0 < n) *(__half2*)&Ch[(size_t)r0 * ncols + col] = __floats2half2_rn(c0, c1);
                if (r1 < n) *(__half2*)&Ch[(size_t)r1 * ncols + col] = __floats2half2_rn(c2, c3);
                plo += c0 * as8[2 * nt] + c1 * as8[2 * nt + 1];
                phi += c2 * as8[2 * nt] + c3 * as8[2 * nt + 1];
                qlo += c0 * ad8[2 * nt] + c1 * ad8[2 * nt + 1];
                qhi += c2 * ad8[2 * nt] + c3 * ad8[2 * nt + 1];
            }
#pragma unroll
            for (int off = 1; off <= 2; off <<= 1) {
                plo += __shfl_xor_sync(0xffffffffu, plo, off);
                phi += __shfl_xor_sync(0xffffffffu, phi, off);
                qlo += __shfl_xor_sync(0xffffffffu, qlo, off);
                qhi += __shfl_xor_sync(0xffffffffu, qhi, off);
            }
            if ((l & 3) == 0) {
                int rr = wr * 32 + mt * 16 + (l >> 2);
                Ses[rr * 2 + wc] = plo;
                Ses[(rr + 8) * 2 + wc] = phi;
                Sed[rr * 2 + wc] = qlo;
                Sed[(rr + 8) * 2 + wc] = qhi;
            }
        }
        __syncthreads();
        if (tid < 128) {
            int row = bm + tid;
            if (row < n) {
                g_es[row * 4 + head] = Ses[tid * 2] + Ses[tid * 2 + 1];
                g_ed[row * 4 + head] = Sed[tid * 2] + Sed[tid * 2 + 1];
            }
        }
    } else {
#pragma unroll
        for (int mt = 0; mt < 2; mt++) {
            int r0 = bm + wr * 32 + mt * 16 + (l >> 2);
            int r1 = r0 + 8;
#pragma unroll
            for (int nt = 0; nt < 4; nt++) {
                int col = bn + wc * 32 + nt * 8 + 2 * (l & 3);
                if (r0 < n) *(float2*)&Cf[(size_t)r0 * ncols + col] =
                    make_float2(c[mt][nt][0], c[mt][nt][1]);
                if (r1 < n) *(float2*)&Cf[(size_t)r1 * ncols + col] =
                    make_float2(c[mt][nt][2], c[mt][nt][3]);
            }
        }
    }
}

// == mega: y=0 placement | y=1..4 W1-GEMM head (+attn) | y=5 skip GEMM ==
// launch_bounds(256,4): cap regs at 64 -> 4 blocks/SM (occ 33.6% -> ~50%)
__global__ void __launch_bounds__(256, 4) mega1_kernel(
    const float* __restrict__ x, const float* __restrict__ W1,
    const float* __restrict__ Wskip,
    const float* __restrict__ asrc, const float* __restrict__ adst,
    const int* __restrict__ ei, int n, int E, int etot)
{
    __shared__ __half As[128 * 72];
    __shared__ __half Bs[64 * 72];
    int y = blockIdx.y;
    if (y == 0) {
        for (int e = blockIdx.x * blockDim.x + threadIdx.x; e < etot;
             e += gridDim.x * blockDim.x) {
            int s, d;
            if (e < E) { s = __ldg(ei + e); d = __ldg(ei + E + e); }
            else       { s = e - E;         d = s; }
            int pos = g_rowptr[d] + g_rank[e];
            g_csrc[pos] = s;
        }
    } else if (y <= 4) {
        gemm_body<true, true>(As, Bs, nullptr, x, W1, nullptr, g_h1h,
                              n, NFIN, NHC, y - 1, blockIdx.x, asrc, adst);
    } else {
        gemm_body<false, true>(As, Bs, nullptr, x, Wskip, g_skip, nullptr,
                               n, NFIN, NC, 0, blockIdx.x, nullptr, nullptr);
    }
}

// ===== layer-2 GEMM (fp16 A) =====
__global__ void __launch_bounds__(256, 4) hgemm2_kernel(
    const __half* __restrict__ Ah, const float* __restrict__ Bf,
    int n, const float* __restrict__ asrc, const float* __restrict__ adst)
{
    __shared__ __half As[128 * 72];
    __shared__ __half Bs[64 * 72];
    gemm_body<true, false>(As, Bs, Ah, nullptr, Bf, nullptr, g_h1h,
                           n, NC, NHC, blockIdx.y, blockIdx.x, asrc, adst);
}

// == fused softmax + gather + BN-stats: warp per dst node, 8-wide pipeline ===
__global__ void __launch_bounds__(256) aggregate_kernel(
    int n, float* __restrict__ sums, float* __restrict__ sumsq)
{
    __shared__ float bsum[NC], bsq[NC];
    const int tid = threadIdx.x;
    if (tid < NC) { bsum[tid] = 0.f; bsq[tid] = 0.f; }
    __syncthreads();

    int w = (blockIdx.x * blockDim.x + tid) >> 5;
    int lane = tid & 31;
    const int h = lane >> 3;
    const int cb = (lane & 7) * 8;
    float a[8] = {0.f, 0.f, 0.f, 0.f, 0.f, 0.f, 0.f, 0.f};
    bool active = (w < n);

    if (active) {
        int beg = g_rowptr[w], end = g_rowptr[w + 1];
        float edv = g_ed[w * 4 + h];
        float s = 0.f;
        const __half* hb = g_h1h + h * 64 + cb;
        float a0 = 0.f, a1 = 0.f, a2 = 0.f, a3 = 0.f;
        float a4 = 0.f, a5 = 0.f, a6 = 0.f, a7 = 0.f;

        int pos = beg;
        for (; pos + 8 <= end; pos += 8) {
            int sv[8];
#pragma unroll
            for (int q = 0; q < 8; q++) sv[q] = g_csrc[pos + q];
            float ev[8];
            uint4 vv[8];
#pragma unroll
            for (int q = 0; q < 8; q++) {
                ev[q] = g_es[sv[q] * 4 + h] + edv;
                vv[q] = *(const uint4*)(hb + (size_t)sv[q] * NHC);
            }
#pragma unroll
            for (int q = 0; q < 8; q++) {
                float e = ev[q];
                e = e > 0.f ? e : 0.2f * e;
                float p = __expf(e);
                s += p;
                float2 f0 = __half22float2(*(__half2*)&vv[q].x);
                float2 f1 = __half22float2(*(__half2*)&vv[q].y);
                float2 f2 = __half22float2(*(__half2*)&vv[q].z);
                float2 f3 = __half22float2(*(__half2*)&vv[q].w);
                a0 += p * f0.x; a1 += p * f0.y; a2 += p * f1.x; a3 += p * f1.y;
                a4 += p * f2.x; a5 += p * f2.y; a6 += p * f3.x; a7 += p * f3.y;
            }
        }
        for (; pos < end; pos++) {
            int s0 = g_csrc[pos];
            float e0 = g_es[s0 * 4 + h] + edv;
            uint4 v0 = *(const uint4*)(hb + (size_t)s0 * NHC);
            e0 = e0 > 0.f ? e0 : 0.2f * e0;
            float p0 = __expf(e0);
            s += p0;
            float2 f0 = __half22float2(*(__half2*)&v0.x);
            float2 f1 = __half22float2(*(__half2*)&v0.y);
            float2 f2 = __half22float2(*(__half2*)&v0.z);
            float2 f3 = __half22float2(*(__half2*)&v0.w);
            a0 += p0 * f0.x; a1 += p0 * f0.y; a2 += p0 * f1.x; a3 += p0 * f1.y;
            a4 += p0 * f2.x; a5 += p0 * f2.y; a6 += p0 * f3.x; a7 += p0 * f3.y;
        }
        float inv = 0.25f / (s + 1e-16f);
        a[0] = a0 * inv; a[1] = a1 * inv; a[2] = a2 * inv; a[3] = a3 * inv;
        a[4] = a4 * inv; a[5] = a5 * inv; a[6] = a6 * inv; a[7] = a7 * inv;
    }
#pragma unroll
    for (int j = 0; j < 8; j++) {
        a[j] += __shfl_xor_sync(0xffffffffu, a[j], 8);
        a[j] += __shfl_xor_sync(0xffffffffu, a[j], 16);
    }
    if (active && lane < 8) {
        *(float4*)&g_acc[w * NC + lane * 8]     = make_float4(a[0], a[1], a[2], a[3]);
        *(float4*)&g_acc[w * NC + lane * 8 + 4] = make_float4(a[4], a[5], a[6], a[7]);
#pragma unroll
        for (int j = 0; j < 8; j++) {
            atomicAdd(&bsum[lane * 8 + j], a[j]);
            atomicAdd(&bsq[lane * 8 + j], a[j] * a[j]);
        }
    }
    __syncthreads();
    if (tid < NC) {
        atomicAdd(&sums[tid], bsum[tid]);
        atomicAdd(&sumsq[tid], bsq[tid]);
    }
}

// ===== fused epilogue 1 (BN finalize inline), float4-vectorized =====
// GAT bias b1/b2 cancels inside BatchNorm (additive constant) -> never applied.
__global__ void fuse1_kernel(const float* __restrict__ bskip,
                             const float* __restrict__ gamma,
                             const float* __restrict__ beta,
                             const float* __restrict__ sums,
                             const float* __restrict__ sumsq,
                             float ninv, int total4)
{
    int i = blockIdx.x * blockDim.x + threadIdx.x;
    if (i >= total4) return;
    int c4 = (i & 15) * 4;
    float4 sm = *(const float4*)&sums[c4];
    float4 sq = *(const float4*)&sumsq[c4];
    float4 gm = *(const float4*)&gamma[c4];
    float4 bt = *(const float4*)&beta[c4];
    float4 bk = *(const float4*)&bskip[c4];
    float4 av = ((const float4*)g_acc)[i];
    float4 sk = ((const float4*)g_skip)[i];
    float mu, var, sc, sh, x;
    float r[4];
    mu = sm.x * ninv; var = sq.x * ninv - mu * mu;
    sc = gm.x * rsqrtf(var + BN_EPS); sh = bt.x - mu * sc;
    x = av.x * sc + sh + sk.x + bk.x; r[0] = gelu_exact(x);
    mu = sm.y * ninv; var = sq.y * ninv - mu * mu;
    sc = gm.y * rsqrtf(var + BN_EPS); sh = bt.y - mu * sc;
    x = av.y * sc + sh + sk.y + bk.y; r[1] = gelu_exact(x);
    mu = sm.z * ninv; var = sq.z * ninv - mu * mu;
    sc = gm.z * rsqrtf(var + BN_EPS); sh = bt.z - mu * sc;
    x = av.z * sc + sh + sk.z + bk.z; r[2] = gelu_exact(x);
    mu = sm.w * ninv; var = sq.w * ninv - mu * mu;
    sc = gm.w * rsqrtf(var + BN_EPS); sh = bt.w - mu * sc;
    x = av.w * sc + sh + sk.w + bk.w; r[3] = gelu_exact(x);
    __half2 h0 = __floats2half2_rn(r[0], r[1]);
    __half2 h1 = __floats2half2_rn(r[2], r[3]);
    ((uint2*)g_hmidh)[i] = make_uint2(*(unsigned*)&h0, *(unsigned*)&h1);
}

// ===== fused epilogue 2 + pool; tail re-zeros cnt & stats for next call =====
__device__ __forceinline__ int lower_bound_dev(const int* arr, int n, int target) {
    int lo = 0, hi = n;
    while (lo < hi) {
        int mid = (lo + hi) >> 1;
        if (arr[mid] < target) lo = mid + 1; else hi = mid;
    }
    return lo;
}

__global__ void fuse2_pool_kernel(const int* __restrict__ batch,
                                  const float* __restrict__ gamma,
                                  const float* __restrict__ beta,
                                  const float* __restrict__ sums,
                                  const float* __restrict__ sumsq,
                                  float ninv,
                                  float* __restrict__ out, int n)
{
    int g = blockIdx.x;
    __shared__ int bounds[2];
    if (threadIdx.x < 2)
        bounds[threadIdx.x] = lower_bound_dev(batch, n, g + threadIdx.x);
    __syncthreads();
    int lo = bounds[0], hi = bounds[1];
    int c = threadIdx.x & 63, rq = threadIdx.x >> 6;
    float mu = sums[c] * ninv;
    float var = sumsq[c] * ninv - mu * mu;
    float sc = gamma[c] * rsqrtf(var + BN_EPS);
    float sh = beta[c] - mu * sc;
    float s = 0.f;
    for (int node = lo + rq; node < hi; node += 4) {
        float res = __half2float(g_hmidh[node * NC + c]);
        float x = g_acc[node * NC + c] * sc + sh + res;
        s += gelu_exact(x);
    }
    __shared__ float red[256];
    red[threadIdx.x] = s;
    __syncthreads();
    if (threadIdx.x < 64) {
        float tot = red[c] + red[c + 64] + red[c + 128] + red[c + 192];
        out[g * NC + c] = tot / fmaxf((float)(hi - lo), 1.f);
    }
    for (int i = blockIdx.x * blockDim.x + threadIdx.x; i < n;
         i += gridDim.x * blockDim.x)
        g_cnt[i] = 0;
    if (blockIdx.x == 0 && threadIdx.x < 4 * NC)
        g_bnstats[threadIdx.x] = 0.f;
}

// ================= launch =================
extern "C" void kernel_launch(void* const* d_in, const int* in_sizes, int n_in,
                              void* d_out, int out_size) {
    const float* x      = (const float*)d_in[0];
    const float* W1     = (const float*)d_in[1];
    const float* a_src1 = (const float*)d_in[2];
    const float* a_dst1 = (const float*)d_in[3];
    const float* Wskip  = (const float*)d_in[5];
    const float* bskip  = (const float*)d_in[6];
    const float* g1     = (const float*)d_in[7];
    const float* be1    = (const float*)d_in[8];
    const float* W2     = (const float*)d_in[9];
    const float* a_src2 = (const float*)d_in[10];
    const float* a_dst2 = (const float*)d_in[11];
    const float* g2     = (const float*)d_in[13];
    const float* be2    = (const float*)d_in[14];
    const int*   ei     = (const int*)d_in[15];
    const int*   batch  = (const int*)d_in[16];
    float* out = (float*)d_out;

    int n = in_sizes[0] / NFIN;
    int E = in_sizes[15] / 2;
    int etot = E + n;
    float ninv = 1.f / (float)n;

    float* p_stats;
    cudaGetSymbolAddress((void**)&p_stats, g_bnstats);
    float* p_sums0  = p_stats;
    float* p_sumsq0 = p_stats + NC;
    float* p_sums1  = p_stats + 2 * NC;
    float* p_sumsq1 = p_stats + 3 * NC;
    __half* p_hmidh;
    cudaGetSymbolAddress((void**)&p_hmidh, g_hmidh);

    int gx = (n + 127) / 128;
    int ab = (n * 32 + 255) / 256;
    int hb = (etot + 2047) / 2048;
    int f4 = n * NC / 4;
    int fb4 = (f4 + 255) / 256;

    hist_scan_kernel<<<hb, 1024>>>(ei, E, etot, n, hb);

    mega1_kernel<<<dim3(gx, 6), 256>>>(x, W1, Wskip, a_src1, a_dst1, ei, n, E, etot);

    aggregate_kernel<<<ab, 256>>>(n, p_sums0, p_sumsq0);
    fuse1_kernel<<<fb4, 256>>>(bskip, g1, be1, p_sums0, p_sumsq0, ninv, f4);

    hgemm2_kernel<<<dim3(gx, 4), 256>>>(p_hmidh, W2, n, a_src2, a_dst2);
    aggregate_kernel<<<ab, 256>>>(n, p_sums1, p_sumsq1);
    fuse2_pool_kernel<<<N_GRAPH, 256>>>(batch, g2, be2, p_sums1, p_sumsq1, ninv, out, n);
}

// round 14
// speedup vs baseline: 1.0923x; 1.0329x over previous
#include <cuda_runtime.h>
#include <cuda_fp16.h>
#include <math.h>

#define N_NODES 20000
#define N_GRAPH 64
#define NH 4
#define NC 64
#define NFIN 128
#define NHC 256
#define E_RAW 320000
#define E_TOT (E_RAW + N_NODES)
#define BN_EPS 1e-5f

// ---------------- scratch (device globals; zero-initialized at load) -------
static __device__ __align__(16) __half g_h1h[N_NODES * NHC];
static __device__ __align__(16) __half g_hmidh[N_NODES * NC];
static __device__ float g_skip[N_NODES * NC];
static __device__ float g_es[N_NODES * NH];
static __device__ float g_ed[N_NODES * NH];
static __device__ float g_acc[N_NODES * NC];
static __device__ float g_bnstats[4 * NC];           // kept zeroed between calls
static __device__ __align__(16) int g_cnt[N_NODES];  // kept zeroed between calls
static __device__ int   g_rowptr[N_NODES + 1];
static __device__ int   g_rank[E_TOT];
static __device__ int   g_csrc[E_TOT];
static __device__ int   g_histdone;                  // kept zeroed between calls

__device__ __forceinline__ float gelu_exact(float x) {
    return 0.5f * x * (1.f + erff(x * 0.70710678118654752440f));
}

__device__ __forceinline__ unsigned smem_u32(const void* p) {
    return (unsigned)__cvta_generic_to_shared(p);
}

__device__ __forceinline__ void ldm_x4(unsigned r[4], unsigned addr) {
    asm volatile("ldmatrix.sync.aligned.m8n8.x4.shared.b16 {%0,%1,%2,%3}, [%4];"
        : "=r"(r[0]), "=r"(r[1]), "=r"(r[2]), "=r"(r[3]) : "r"(addr));
}
__device__ __forceinline__ void ldm_x2t(unsigned r[2], unsigned addr) {
    asm volatile("ldmatrix.sync.aligned.m8n8.x2.trans.shared.b16 {%0,%1}, [%2];"
        : "=r"(r[0]), "=r"(r[1]) : "r"(addr));
}
__device__ __forceinline__ void mma16816(float c[4], const unsigned a[4], const unsigned b[2]) {
    asm volatile("mma.sync.aligned.m16n8k16.row.col.f32.f16.f16.f32 "
        "{%0,%1,%2,%3}, {%4,%5,%6,%7}, {%8,%9}, {%0,%1,%2,%3};"
        : "+f"(c[0]), "+f"(c[1]), "+f"(c[2]), "+f"(c[3])
        : "r"(a[0]), "r"(a[1]), "r"(a[2]), "r"(a[3]), "r"(b[0]), "r"(b[1]));
}

__device__ __forceinline__ uint4 pack8h(float4 fa, float4 fb) {
    __half2 h0 = __floats2half2_rn(fa.x, fa.y);
    __half2 h1 = __floats2half2_rn(fa.z, fa.w);
    __half2 h2 = __floats2half2_rn(fb.x, fb.y);
    __half2 h3 = __floats2half2_rn(fb.z, fb.w);
    return make_uint4(*(unsigned*)&h0, *(unsigned*)&h1, *(unsigned*)&h2, *(unsigned*)&h3);
}

// ===== hist + scan fused =====
__global__ void __launch_bounds__(1024) hist_scan_kernel(
    const int* __restrict__ ei, int E, int etot, int n, int nblocks)
{
    int t = threadIdx.x;
    for (int e = blockIdx.x * 1024 + t; e < etot; e += nblocks * 1024) {
        int d = (e < E) ? ei[E + e] : (e - E);
        g_rank[e] = atomicAdd(&g_cnt[d], 1);
    }
    __threadfence();
    __shared__ int isLast;
    if (t == 0) isLast = (atomicAdd(&g_histdone, 1) == nblocks - 1);
    __syncthreads();
    if (!isLast) return;
    if (t == 0) g_histdone = 0;

    const int PER = 20;
    int lane = t & 31, wid = t >> 5;
    int base = t * PER;
    int v[PER];
    if (base + PER <= n) {
        const int4* p = (const int4*)(g_cnt + base);
#pragma unroll
        for (int i = 0; i < 5; i++) {
            int4 q = p[i];
            v[4 * i] = q.x; v[4 * i + 1] = q.y; v[4 * i + 2] = q.z; v[4 * i + 3] = q.w;
        }
    } else {
#pragma unroll
        for (int i = 0; i < PER; i++) v[i] = (base + i < n) ? g_cnt[base + i] : 0;
    }
    int sum = 0;
#pragma unroll
    for (int i = 0; i < PER; i++) sum += v[i];
    int s = sum;
#pragma unroll
    for (int o = 1; o < 32; o <<= 1) {
        int x = __shfl_up_sync(0xffffffffu, s, o);
        if (lane >= o) s += x;
    }
    __shared__ int wp[32];
    if (lane == 31) wp[wid] = s;
    __syncthreads();
    if (wid == 0) {
        int orig = wp[lane];
        int ws = orig;
#pragma unroll
        for (int o = 1; o < 32; o <<= 1) {
            int x = __shfl_up_sync(0xffffffffu, ws, o);
            if (lane >= o) ws += x;
        }
        wp[lane] = ws - orig;
    }
    __syncthreads();
    int run = wp[wid] + s - sum;
#pragma unroll
    for (int i = 0; i < PER; i++) {
        if (base + i < n) g_rowptr[base + i] = run;
        run += v[i];
    }
    if (t == 1023) g_rowptr[n] = run;
}

// ========== HMMA GEMM body (two-stage K=64 staging; STS.128 tile stores) ====
template <bool ATTN, bool AF32>
__device__ __forceinline__ void gemm_body(
    __half* As, __half* Bs,
    const __half* __restrict__ Ah, const float* __restrict__ Af,
    const float* __restrict__ Bf,
    float* __restrict__ Cf, __half* __restrict__ Ch,
    int n, int K, int ncols, int head, int bx,
    const float* __restrict__ asrc, const float* __restrict__ adst)
{
    const int tid = threadIdx.x;
    const int l = tid & 31, w = tid >> 5;
    const int wr = w >> 1, wc = w & 1;
    const int bm = bx * 128, bn = head * 64;

    float c[2][4][4];
#pragma unroll
    for (int mt = 0; mt < 2; mt++)
#pragma unroll
        for (int nt = 0; nt < 4; nt++)
#pragma unroll
            for (int j = 0; j < 4; j++) c[mt][nt][j] = 0.f;

    for (int k0 = 0; k0 < K; k0 += 64) {
        {
            int rlocal = tid >> 1;
            int row = bm + rlocal;
            int colh = (tid & 1) * 32;
            bool ok = row < n;
            if (AF32) {
                const float4* src = (const float4*)(Af + (size_t)row * K + k0 + colh);
                uint4* dstp = (uint4*)(As + rlocal * 72 + colh);
                float4 z4 = make_float4(0.f, 0.f, 0.f, 0.f);
#pragma unroll
                for (int u = 0; u < 4; u++) {
                    float4 fa = ok ? src[2 * u] : z4;
                    float4 fb = ok ? src[2 * u + 1] : z4;
                    dstp[u] = pack8h(fa, fb);
                }
            } else {
                uint4 z = make_uint4(0, 0, 0, 0);
                const uint4* src = (const uint4*)(Ah + (size_t)row * K + k0 + colh);
                uint4 v0 = ok ? src[0] : z;
                uint4 v1 = ok ? src[1] : z;
                uint4 v2 = ok ? src[2] : z;
                uint4 v3 = ok ? src[3] : z;
                uint4* dstp = (uint4*)(As + rlocal * 72 + colh);
                dstp[0] = v0; dstp[1] = v1; dstp[2] = v2; dstp[3] = v3;
            }
        }
        {
            int row = tid >> 2, colh = (tid & 3) * 16;
            const float4* src = (const float4*)(Bf + (size_t)(k0 + row) * ncols + bn + colh);
            uint4* dstp = (uint4*)(Bs + row * 72 + colh);
#pragma unroll
            for (int u = 0; u < 2; u++) {
                float4 fa = src[2 * u];
                float4 fb = src[2 * u + 1];
                dstp[u] = pack8h(fa, fb);
            }
        }
        __syncthreads();
#pragma unroll
        for (int kk = 0; kk < 4; kk++) {
            unsigned af[2][4];
#pragma unroll
            for (int mt = 0; mt < 2; mt++) {
                int rowA = wr * 32 + mt * 16 + (l & 15);
                int colA = kk * 16 + ((l >> 4) << 3);
                ldm_x4(af[mt], smem_u32(As + rowA * 72 + colA));
            }
            unsigned bf[4][2];
#pragma unroll
            for (int nt = 0; nt < 4; nt++) {
                int rowB = kk * 16 + (l & 15);
                int colB = wc * 32 + nt * 8;
                ldm_x2t(bf[nt], smem_u32(Bs + rowB * 72 + colB));
            }
#pragma unroll
            for (int mt = 0; mt < 2; mt++)
#pragma unroll
                for (int nt = 0; nt < 4; nt++)
                    mma16816(c[mt][nt], af[mt], bf[nt]);
        }
        __syncthreads();
    }

    if (ATTN) {
        float as8[8], ad8[8];
        int cb = wc * 32 + 2 * (l & 3);
#pragma unroll
        for (int nt = 0; nt < 4; nt++) {
            as8[2 * nt]     = asrc[bn + cb + nt * 8];
            as8[2 * nt + 1] = asrc[bn + cb + nt * 8 + 1];
            ad8[2 * nt]     = adst[bn + cb + nt * 8];
            ad8[2 * nt + 1] = adst[bn + cb + nt * 8 + 1];
        }
        float* Ses = (float*)As;
        float* Sed = Ses + 256;
#pragma unroll
        for (int mt = 0; mt < 2; mt++) {
            int r0 = bm + wr * 32 + mt * 16 + (l >> 2);
            int r1 = r0 + 8;
            float plo = 0.f, phi = 0.f, qlo = 0.f, qhi = 0.f;
#pragma unroll
            for (int nt = 0; nt < 4; nt++) {
                float c0 = c[mt][nt][0], c1 = c[mt][nt][1];
                float c2 = c[mt][nt][2], c3 = c[mt][nt][3];
                int col = bn + wc * 32 + nt * 8 + 2 * (l & 3);
                if (r0 < n) *(__half2*)&Ch[(size_t)r0 * ncols + col] = __floats2half2_rn(c0, c1);
                if (r1 < n) *(__half2*)&Ch[(size_t)r1 * ncols + col] = __floats2half2_rn(c2, c3);
                plo += c0 * as8[2 * nt] + c1 * as8[2 * nt + 1];
                phi += c2 * as8[2 * nt] + c3 * as8[2 * nt + 1];
                qlo += c0 * ad8[2 * nt] + c1 * ad8[2 * nt + 1];
                qhi += c2 * ad8[2 * nt] + c3 * ad8[2 * nt + 1];
            }
#pragma unroll
            for (int off = 1; off <= 2; off <<= 1) {
                plo += __shfl_xor_sync(0xffffffffu, plo, off);
                phi += __shfl_xor_sync(0xffffffffu, phi, off);
                qlo += __shfl_xor_sync(0xffffffffu, qlo, off);
                qhi += __shfl_xor_sync(0xffffffffu, qhi, off);
            }
            if ((l & 3) == 0) {
                int rr = wr * 32 + mt * 16 + (l >> 2);
                Ses[rr * 2 + wc] = plo;
                Ses[(rr + 8) * 2 + wc] = phi;
                Sed[rr * 2 + wc] = qlo;
                Sed[(rr + 8) * 2 + wc] = qhi;
            }
        }
        __syncthreads();
        if (tid < 128) {
            int row = bm + tid;
            if (row < n) {
                g_es[row * 4 + head] = Ses[tid * 2] + Ses[tid * 2 + 1];
                g_ed[row * 4 + head] = Sed[tid * 2] + Sed[tid * 2 + 1];
            }
        }
    } else {
#pragma unroll
        for (int mt = 0; mt < 2; mt++) {
            int r0 = bm + wr * 32 + mt * 16 + (l >> 2);
            int r1 = r0 + 8;
#pragma unroll
            for (int nt = 0; nt < 4; nt++) {
                int col = bn + wc * 32 + nt * 8 + 2 * (l & 3);
                if (r0 < n) *(float2*)&Cf[(size_t)r0 * ncols + col] =
                    make_float2(c[mt][nt][0], c[mt][nt][1]);
                if (r1 < n) *(float2*)&Cf[(size_t)r1 * ncols + col] =
                    make_float2(c[mt][nt][2], c[mt][nt][3]);
            }
        }
    }
}

// == mega: y=0 placement | y=1..4 W1-GEMM head (+attn) | y=5 skip GEMM ==
__global__ void __launch_bounds__(256) mega1_kernel(
    const float* __restrict__ x, const float* __restrict__ W1,
    const float* __restrict__ Wskip,
    const float* __restrict__ asrc, const float* __restrict__ adst,
    const int* __restrict__ ei, int n, int E, int etot)
{
    __shared__ __half As[128 * 72];
    __shared__ __half Bs[64 * 72];
    int y = blockIdx.y;
    if (y == 0) {
        for (int e = blockIdx.x * blockDim.x + threadIdx.x; e < etot;
             e += gridDim.x * blockDim.x) {
            int s, d;
            if (e < E) { s = __ldg(ei + e); d = __ldg(ei + E + e); }
            else       { s = e - E;         d = s; }
            int pos = g_rowptr[d] + g_rank[e];
            g_csrc[pos] = s;
        }
    } else if (y <= 4) {
        gemm_body<true, true>(As, Bs, nullptr, x, W1, nullptr, g_h1h,
                              n, NFIN, NHC, y - 1, blockIdx.x, asrc, adst);
    } else {
        gemm_body<false, true>(As, Bs, nullptr, x, Wskip, g_skip, nullptr,
                               n, NFIN, NC, 0, blockIdx.x, nullptr, nullptr);
    }
}

// ===== layer-2 GEMM (fp16 A) =====
__global__ void __launch_bounds__(256) hgemm2_kernel(
    const __half* __restrict__ Ah, const float* __restrict__ Bf,
    int n, const float* __restrict__ asrc, const float* __restrict__ adst)
{
    __shared__ __half As[128 * 72];
    __shared__ __half Bs[64 * 72];
    gemm_body<true, false>(As, Bs, Ah, nullptr, Bf, nullptr, g_h1h,
                           n, NC, NHC, blockIdx.y, blockIdx.x, asrc, adst);
}

// == fused softmax + gather + BN-stats: warp per dst node, 8-wide pipeline ===
__global__ void __launch_bounds__(256) aggregate_kernel(
    int n, float* __restrict__ sums, float* __restrict__ sumsq)
{
    __shared__ float bsum[NC], bsq[NC];
    const int tid = threadIdx.x;
    if (tid < NC) { bsum[tid] = 0.f; bsq[tid] = 0.f; }
    __syncthreads();

    int w = (blockIdx.x * blockDim.x + tid) >> 5;
    int lane = tid & 31;
    const int h = lane >> 3;
    const int cb = (lane & 7) * 8;
    float a[8] = {0.f, 0.f, 0.f, 0.f, 0.f, 0.f, 0.f, 0.f};
    bool active = (w < n);

    if (active) {
        int beg = g_rowptr[w], end = g_rowptr[w + 1];
        float edv = g_ed[w * 4 + h];
        float s = 0.f;
        const __half* hb = g_h1h + h * 64 + cb;
        float a0 = 0.f, a1 = 0.f, a2 = 0.f, a3 = 0.f;
        float a4 = 0.f, a5 = 0.f, a6 = 0.f, a7 = 0.f;

        int pos = beg;
        for (; pos + 8 <= end; pos += 8) {
            int sv[8];
#pragma unroll
            for (int q = 0; q < 8; q++) sv[q] = g_csrc[pos + q];
            float ev[8];
            uint4 vv[8];
#pragma unroll
            for (int q = 0; q < 8; q++) {
                ev[q] = g_es[sv[q] * 4 + h] + edv;
                vv[q] = *(const uint4*)(hb + (size_t)sv[q] * NHC);
            }
#pragma unroll
            for (int q = 0; q < 8; q++) {
                float e = ev[q];
                e = e > 0.f ? e : 0.2f * e;
                float p = __expf(e);
                s += p;
                float2 f0 = __half22float2(*(__half2*)&vv[q].x);
                float2 f1 = __half22float2(*(__half2*)&vv[q].y);
                float2 f2 = __half22float2(*(__half2*)&vv[q].z);
                float2 f3 = __half22float2(*(__half2*)&vv[q].w);
                a0 += p * f0.x; a1 += p * f0.y; a2 += p * f1.x; a3 += p * f1.y;
                a4 += p * f2.x; a5 += p * f2.y; a6 += p * f3.x; a7 += p * f3.y;
            }
        }
        for (; pos < end; pos++) {
            int s0 = g_csrc[pos];
            float e0 = g_es[s0 * 4 + h] + edv;
            uint4 v0 = *(const uint4*)(hb + (size_t)s0 * NHC);
            e0 = e0 > 0.f ? e0 : 0.2f * e0;
            float p0 = __expf(e0);
            s += p0;
            float2 f0 = __half22float2(*(__half2*)&v0.x);
            float2 f1 = __half22float2(*(__half2*)&v0.y);
            float2 f2 = __half22float2(*(__half2*)&v0.z);
            float2 f3 = __half22float2(*(__half2*)&v0.w);
            a0 += p0 * f0.x; a1 += p0 * f0.y; a2 += p0 * f1.x; a3 += p0 * f1.y;
            a4 += p0 * f2.x; a5 += p0 * f2.y; a6 += p0 * f3.x; a7 += p0 * f3.y;
        }
        float inv = 0.25f / (s + 1e-16f);
        a[0] = a0 * inv; a[1] = a1 * inv; a[2] = a2 * inv; a[3] = a3 * inv;
        a[4] = a4 * inv; a[5] = a5 * inv; a[6] = a6 * inv; a[7] = a7 * inv;
    }
#pragma unroll
    for (int j = 0; j < 8; j++) {
        a[j] += __shfl_xor_sync(0xffffffffu, a[j], 8);
        a[j] += __shfl_xor_sync(0xffffffffu, a[j], 16);
    }
    if (active && lane < 8) {
        *(float4*)&g_acc[w * NC + lane * 8]     = make_float4(a[0], a[1], a[2], a[3]);
        *(float4*)&g_acc[w * NC + lane * 8 + 4] = make_float4(a[4], a[5], a[6], a[7]);
#pragma unroll
        for (int j = 0; j < 8; j++) {
            atomicAdd(&bsum[lane * 8 + j], a[j]);
            atomicAdd(&bsq[lane * 8 + j], a[j] * a[j]);
        }
    }
    __syncthreads();
    if (tid < NC) {
        atomicAdd(&sums[tid], bsum[tid]);
        atomicAdd(&sumsq[tid], bsq[tid]);
    }
}

// ===== fused epilogue 1 (BN finalize inline), 2x float4 per thread =====
// GAT bias b1/b2 cancels inside BatchNorm (additive constant) -> never applied.
__global__ void fuse1_kernel(const float* __restrict__ bskip,
                             const float* __restrict__ gamma,
                             const float* __restrict__ beta,
                             const float* __restrict__ sums,
                             const float* __restrict__ sumsq,
                             float ninv, int total4)
{
    int i0 = 2 * (blockIdx.x * blockDim.x + threadIdx.x);
#pragma unroll
    for (int rep = 0; rep < 2; rep++) {
        int i = i0 + rep;
        if (i >= total4) return;
        int c4 = (i & 15) * 4;
        float4 sm = *(const float4*)&sums[c4];
        float4 sq = *(const float4*)&sumsq[c4];
        float4 gm = *(const float4*)&gamma[c4];
        float4 bt = *(const float4*)&beta[c4];
        float4 bk = *(const float4*)&bskip[c4];
        float4 av = ((const float4*)g_acc)[i];
        float4 sk = ((const float4*)g_skip)[i];
        float mu, var, sc, sh, x;
        float r[4];
        mu = sm.x * ninv; var = sq.x * ninv - mu * mu;
        sc = gm.x * rsqrtf(var + BN_EPS); sh = bt.x - mu * sc;
        x = av.x * sc + sh + sk.x + bk.x; r[0] = gelu_exact(x);
        mu = sm.y * ninv; var = sq.y * ninv - mu * mu;
        sc = gm.y * rsqrtf(var + BN_EPS); sh = bt.y - mu * sc;
        x = av.y * sc + sh + sk.y + bk.y; r[1] = gelu_exact(x);
        mu = sm.z * ninv; var = sq.z * ninv - mu * mu;
        sc = gm.z * rsqrtf(var + BN_EPS); sh = bt.z - mu * sc;
        x = av.z * sc + sh + sk.z + bk.z; r[2] = gelu_exact(x);
        mu = sm.w * ninv; var = sq.w * ninv - mu * mu;
        sc = gm.w * rsqrtf(var + BN_EPS); sh = bt.w - mu * sc;
        x = av.w * sc + sh + sk.w + bk.w; r[3] = gelu_exact(x);
        __half2 h0 = __floats2half2_rn(r[0], r[1]);
        __half2 h1 = __floats2half2_rn(r[2], r[3]);
        ((uint2*)g_hmidh)[i] = make_uint2(*(unsigned*)&h0, *(unsigned*)&h1);
    }
}

// ===== fused epilogue 2 + pool; tail re-zeros cnt & stats for next call =====
__device__ __forceinline__ int lower_bound_dev(const int* arr, int n, int target) {
    int lo = 0, hi = n;
    while (lo < hi) {
        int mid = (lo + hi) >> 1;
        if (arr[mid] < target) lo = mid + 1; else hi = mid;
    }
    return lo;
}

__global__ void fuse2_pool_kernel(const int* __restrict__ batch,
                                  const float* __restrict__ gamma,
                                  const float* __restrict__ beta,
                                  const float* __restrict__ sums,
                                  const float* __restrict__ sumsq,
                                  float ninv,
                                  float* __restrict__ out, int n)
{
    int g = blockIdx.x;
    __shared__ int bounds[2];
    if (threadIdx.x < 2)
        bounds[threadIdx.x] = lower_bound_dev(batch, n, g + threadIdx.x);
    __syncthreads();
    int lo = bounds[0], hi = bounds[1];
    int c = threadIdx.x & 63, rq = threadIdx.x >> 6;
    float mu = sums[c] * ninv;
    float var = sumsq[c] * ninv - mu * mu;
    float sc = gamma[c] * rsqrtf(var + BN_EPS);
    float sh = beta[c] - mu * sc;
    float s = 0.f;
    for (int node = lo + rq; node < hi; node += 4) {
        float res = __half2float(g_hmidh[node * NC + c]);
        float x = g_acc[node * NC + c] * sc + sh + res;
        s += gelu_exact(x);
    }
    __shared__ float red[256];
    red[threadIdx.x] = s;
    __syncthreads();
    if (threadIdx.x < 64) {
        float tot = red[c] + red[c + 64] + red[c + 128] + red[c + 192];
        out[g * NC + c] = tot / fmaxf((float)(hi - lo), 1.f);
    }
    for (int i = blockIdx.x * blockDim.x + threadIdx.x; i < n;
         i += gridDim.x * blockDim.x)
        g_cnt[i] = 0;
    if (blockIdx.x == 0 && threadIdx.x < 4 * NC)
        g_bnstats[threadIdx.x] = 0.f;
}

// ================= launch =================
extern "C" void kernel_launch(void* const* d_in, const int* in_sizes, int n_in,
                              void* d_out, int out_size) {
    const float* x      = (const float*)d_in[0];
    const float* W1     = (const float*)d_in[1];
    const float* a_src1 = (const float*)d_in[2];
    const float* a_dst1 = (const float*)d_in[3];
    const float* Wskip  = (const float*)d_in[5];
    const float* bskip  = (const float*)d_in[6];
    const float* g1     = (const float*)d_in[7];
    const float* be1    = (const float*)d_in[8];
    const float* W2     = (const float*)d_in[9];
    const float* a_src2 = (const float*)d_in[10];
    const float* a_dst2 = (const float*)d_in[11];
    const float* g2     = (const float*)d_in[13];
    const float* be2    = (const float*)d_in[14];
    const int*   ei     = (const int*)d_in[15];
    const int*   batch  = (const int*)d_in[16];
    float* out = (float*)d_out;

    int n = in_sizes[0] / NFIN;
    int E = in_sizes[15] / 2;
    int etot = E + n;
    float ninv = 1.f / (float)n;

    float* p_stats;
    cudaGetSymbolAddress((void**)&p_stats, g_bnstats);
    float* p_sums0  = p_stats;
    float* p_sumsq0 = p_stats + NC;
    float* p_sums1  = p_stats + 2 * NC;
    float* p_sumsq1 = p_stats + 3 * NC;
    __half* p_hmidh;
    cudaGetSymbolAddress((void**)&p_hmidh, g_hmidh);

    int gx = (n + 127) / 128;
    int ab = (n * 32 + 255) / 256;
    int hb = (etot + 2047) / 2048;
    int f4 = n * NC / 4;
    int fb4 = (f4 / 2 + 255) / 256;

    hist_scan_kernel<<<hb, 1024>>>(ei, E, etot, n, hb);

    mega1_kernel<<<dim3(gx, 6), 256>>>(x, W1, Wskip, a_src1, a_dst1, ei, n, E, etot);

    aggregate_kernel<<<ab, 256>>>(n, p_sums0, p_sumsq0);
    fuse1_kernel<<<fb4, 256>>>(bskip, g1, be1, p_sums0, p_sumsq0, ninv, f4);

    hgemm2_kernel<<<dim3(gx, 4), 256>>>(p_hmidh, W2, n, a_src2, a_dst2);
    aggregate_kernel<<<ab, 256>>>(n, p_sums1, p_sumsq1);
    fuse2_pool_kernel<<<N_GRAPH, 256>>>(batch, g2, be2, p_sums1, p_sumsq1, ninv, out, n);
}

// round 15
// speedup vs baseline: 1.1088x; 1.0151x over previous
#include <cuda_runtime.h>
#include <cuda_fp16.h>
#include <math.h>

#define N_NODES 20000
#define N_GRAPH 64
#define NH 4
#define NC 64
#define NFIN 128
#define NHC 256
#define E_RAW 320000
#define E_TOT (E_RAW + N_NODES)
#define BN_EPS 1e-5f

// ---------------- scratch (device globals; zero-initialized at load) -------
static __device__ __align__(16) __half g_h1h[N_NODES * NHC];
static __device__ __align__(16) __half g_hmidh[N_NODES * NC];
static __device__ float g_skip[N_NODES * NC];
static __device__ float g_es[N_NODES * NH];
static __device__ float g_ed[N_NODES * NH];
static __device__ float g_acc[N_NODES * NC];
static __device__ float g_bnstats[4 * NC];           // kept zeroed between calls
static __device__ __align__(16) int g_cnt[N_NODES];  // kept zeroed between calls
static __device__ int   g_rowptr[N_NODES + 1];
static __device__ int   g_rank[E_TOT];
static __device__ int   g_csrc[E_TOT];
static __device__ int   g_histdone;                  // kept zeroed between calls

__device__ __forceinline__ float gelu_exact(float x) {
    return 0.5f * x * (1.f + erff(x * 0.70710678118654752440f));
}

__device__ __forceinline__ unsigned smem_u32(const void* p) {
    return (unsigned)__cvta_generic_to_shared(p);
}

__device__ __forceinline__ void ldm_x4(unsigned r[4], unsigned addr) {
    asm volatile("ldmatrix.sync.aligned.m8n8.x4.shared.b16 {%0,%1,%2,%3}, [%4];"
        : "=r"(r[0]), "=r"(r[1]), "=r"(r[2]), "=r"(r[3]) : "r"(addr));
}
__device__ __forceinline__ void ldm_x2t(unsigned r[2], unsigned addr) {
    asm volatile("ldmatrix.sync.aligned.m8n8.x2.trans.shared.b16 {%0,%1}, [%2];"
        : "=r"(r[0]), "=r"(r[1]) : "r"(addr));
}
__device__ __forceinline__ void mma16816(float c[4], const unsigned a[4], const unsigned b[2]) {
    asm volatile("mma.sync.aligned.m16n8k16.row.col.f32.f16.f16.f32 "
        "{%0,%1,%2,%3}, {%4,%5,%6,%7}, {%8,%9}, {%0,%1,%2,%3};"
        : "+f"(c[0]), "+f"(c[1]), "+f"(c[2]), "+f"(c[3])
        : "r"(a[0]), "r"(a[1]), "r"(a[2]), "r"(a[3]), "r"(b[0]), "r"(b[1]));
}

__device__ __forceinline__ uint4 pack8h(float4 fa, float4 fb) {
    __half2 h0 = __floats2half2_rn(fa.x, fa.y);
    __half2 h1 = __floats2half2_rn(fa.z, fa.w);
    __half2 h2 = __floats2half2_rn(fb.x, fb.y);
    __half2 h3 = __floats2half2_rn(fb.z, fb.w);
    return make_uint4(*(unsigned*)&h0, *(unsigned*)&h1, *(unsigned*)&h2, *(unsigned*)&h3);
}

// ===== hist + scan fused =====
__global__ void __launch_bounds__(1024) hist_scan_kernel(
    const int* __restrict__ ei, int E, int etot, int n, int nblocks)
{
    int t = threadIdx.x;
    for (int e = blockIdx.x * 1024 + t; e < etot; e += nblocks * 1024) {
        int d = (e < E) ? ei[E + e] : (e - E);
        g_rank[e] = atomicAdd(&g_cnt[d], 1);
    }
    __threadfence();
    __shared__ int isLast;
    if (t == 0) isLast = (atomicAdd(&g_histdone, 1) == nblocks - 1);
    __syncthreads();
    if (!isLast) return;
    if (t == 0) g_histdone = 0;

    const int PER = 20;
    int lane = t & 31, wid = t >> 5;
    int base = t * PER;
    int v[PER];
    if (base + PER <= n) {
        const int4* p = (const int4*)(g_cnt + base);
#pragma unroll
        for (int i = 0; i < 5; i++) {
            int4 q = p[i];
            v[4 * i] = q.x; v[4 * i + 1] = q.y; v[4 * i + 2] = q.z; v[4 * i + 3] = q.w;
        }
    } else {
#pragma unroll
        for (int i = 0; i < PER; i++) v[i] = (base + i < n) ? g_cnt[base + i] : 0;
    }
    int sum = 0;
#pragma unroll
    for (int i = 0; i < PER; i++) sum += v[i];
    int s = sum;
#pragma unroll
    for (int o = 1; o < 32; o <<= 1) {
        int x = __shfl_up_sync(0xffffffffu, s, o);
        if (lane >= o) s += x;
    }
    __shared__ int wp[32];
    if (lane == 31) wp[wid] = s;
    __syncthreads();
    if (wid == 0) {
        int orig = wp[lane];
        int ws = orig;
#pragma unroll
        for (int o = 1; o < 32; o <<= 1) {
            int x = __shfl_up_sync(0xffffffffu, ws, o);
            if (lane >= o) ws += x;
        }
        wp[lane] = ws - orig;
    }
    __syncthreads();
    int run = wp[wid] + s - sum;
#pragma unroll
    for (int i = 0; i < PER; i++) {
        if (base + i < n) g_rowptr[base + i] = run;
        run += v[i];
    }
    if (t == 1023) g_rowptr[n] = run;
}

// ========== HMMA GEMM body (two-stage K=64 staging; STS.128 tile stores) ====
template <bool ATTN, bool AF32>
__device__ __forceinline__ void gemm_body(
    __half* As, __half* Bs,
    const __half* __restrict__ Ah, const float* __restrict__ Af,
    const float* __restrict__ Bf,
    float* __restrict__ Cf, __half* __restrict__ Ch,
    int n, int K, int ncols, int head, int bx,
    const float* __restrict__ asrc, const float* __restrict__ adst)
{
    const int tid = threadIdx.x;
    const int l = tid & 31, w = tid >> 5;
    const int wr = w >> 1, wc = w & 1;
    const int bm = bx * 128, bn = head * 64;

    float c[2][4][4];
#pragma unroll
    for (int mt = 0; mt < 2; mt++)
#pragma unroll
        for (int nt = 0; nt < 4; nt++)
#pragma unroll
            for (int j = 0; j < 4; j++) c[mt][nt][j] = 0.f;

    for (int k0 = 0; k0 < K; k0 += 64) {
        {
            int rlocal = tid >> 1;
            int row = bm + rlocal;
            int colh = (tid & 1) * 32;
            bool ok = row < n;
            if (AF32) {
                const float4* src = (const float4*)(Af + (size_t)row * K + k0 + colh);
                uint4* dstp = (uint4*)(As + rlocal * 72 + colh);
                float4 z4 = make_float4(0.f, 0.f, 0.f, 0.f);
#pragma unroll
                for (int u = 0; u < 4; u++) {
                    float4 fa = ok ? src[2 * u] : z4;
                    float4 fb = ok ? src[2 * u + 1] : z4;
                    dstp[u] = pack8h(fa, fb);
                }
            } else {
                uint4 z = make_uint4(0, 0, 0, 0);
                const uint4* src = (const uint4*)(Ah + (size_t)row * K + k0 + colh);
                uint4 v0 = ok ? src[0] : z;
                uint4 v1 = ok ? src[1] : z;
                uint4 v2 = ok ? src[2] : z;
                uint4 v3 = ok ? src[3] : z;
                uint4* dstp = (uint4*)(As + rlocal * 72 + colh);
                dstp[0] = v0; dstp[1] = v1; dstp[2] = v2; dstp[3] = v3;
            }
        }
        {
            int row = tid >> 2, colh = (tid & 3) * 16;
            const float4* src = (const float4*)(Bf + (size_t)(k0 + row) * ncols + bn + colh);
            uint4* dstp = (uint4*)(Bs + row * 72 + colh);
#pragma unroll
            for (int u = 0; u < 2; u++) {
                float4 fa = src[2 * u];
                float4 fb = src[2 * u + 1];
                dstp[u] = pack8h(fa, fb);
            }
        }
        __syncthreads();
#pragma unroll
        for (int kk = 0; kk < 4; kk++) {
            unsigned af[2][4];
#pragma unroll
            for (int mt = 0; mt < 2; mt++) {
                int rowA = wr * 32 + mt * 16 + (l & 15);
                int colA = kk * 16 + ((l >> 4) << 3);
                ldm_x4(af[mt], smem_u32(As + rowA * 72 + colA));
            }
            unsigned bf[4][2];
#pragma unroll
            for (int nt = 0; nt < 4; nt++) {
                int rowB = kk * 16 + (l & 15);
                int colB = wc * 32 + nt * 8;
                ldm_x2t(bf[nt], smem_u32(Bs + rowB * 72 + colB));
            }
#pragma unroll
            for (int mt = 0; mt < 2; mt++)
#pragma unroll
                for (int nt = 0; nt < 4; nt++)
                    mma16816(c[mt][nt], af[mt], bf[nt]);
        }
        __syncthreads();
    }

    if (ATTN) {
        float as8[8], ad8[8];
        int cb = wc * 32 + 2 * (l & 3);
#pragma unroll
        for (int nt = 0; nt < 4; nt++) {
            as8[2 * nt]     = asrc[bn + cb + nt * 8];
            as8[2 * nt + 1] = asrc[bn + cb + nt * 8 + 1];
            ad8[2 * nt]     = adst[bn + cb + nt * 8];
            ad8[2 * nt + 1] = adst[bn + cb + nt * 8 + 1];
        }
        float* Ses = (float*)As;
        float* Sed = Ses + 256;
#pragma unroll
        for (int mt = 0; mt < 2; mt++) {
            int r0 = bm + wr * 32 + mt * 16 + (l >> 2);
            int r1 = r0 + 8;
            float plo = 0.f, phi = 0.f, qlo = 0.f, qhi = 0.f;
#pragma unroll
            for (int nt = 0; nt < 4; nt++) {
                float c0 = c[mt][nt][0], c1 = c[mt][nt][1];
                float c2 = c[mt][nt][2], c3 = c[mt][nt][3];
                int col = bn + wc * 32 + nt * 8 + 2 * (l & 3);
                if (r0 < n) *(__half2*)&Ch[(size_t)r0 * ncols + col] = __floats2half2_rn(c0, c1);
                if (r1 < n) *(__half2*)&Ch[(size_t)r1 * ncols + col] = __floats2half2_rn(c2, c3);
                plo += c0 * as8[2 * nt] + c1 * as8[2 * nt + 1];
                phi += c2 * as8[2 * nt] + c3 * as8[2 * nt + 1];
                qlo += c0 * ad8[2 * nt] + c1 * ad8[2 * nt + 1];
                qhi += c2 * ad8[2 * nt] + c3 * ad8[2 * nt + 1];
            }
#pragma unroll
            for (int off = 1; off <= 2; off <<= 1) {
                plo += __shfl_xor_sync(0xffffffffu, plo, off);
                phi += __shfl_xor_sync(0xffffffffu, phi, off);
                qlo += __shfl_xor_sync(0xffffffffu, qlo, off);
                qhi += __shfl_xor_sync(0xffffffffu, qhi, off);
            }
            if ((l & 3) == 0) {
                int rr = wr * 32 + mt * 16 + (l >> 2);
                Ses[rr * 2 + wc] = plo;
                Ses[(rr + 8) * 2 + wc] = phi;
                Sed[rr * 2 + wc] = qlo;
                Sed[(rr + 8) * 2 + wc] = qhi;
            }
        }
        __syncthreads();
        if (tid < 128) {
            int row = bm + tid;
            if (row < n) {
                g_es[row * 4 + head] = Ses[tid * 2] + Ses[tid * 2 + 1];
                g_ed[row * 4 + head] = Sed[tid * 2] + Sed[tid * 2 + 1];
            }
        }
    } else {
#pragma unroll
        for (int mt = 0; mt < 2; mt++) {
            int r0 = bm + wr * 32 + mt * 16 + (l >> 2);
            int r1 = r0 + 8;
#pragma unroll
            for (int nt = 0; nt < 4; nt++) {
                int col = bn + wc * 32 + nt * 8 + 2 * (l & 3);
                if (r0 < n) *(float2*)&Cf[(size_t)r0 * ncols + col] =
                    make_float2(c[mt][nt][0], c[mt][nt][1]);
                if (r1 < n) *(float2*)&Cf[(size_t)r1 * ncols + col] =
                    make_float2(c[mt][nt][2], c[mt][nt][3]);
            }
        }
    }
}

// == mega: y=0 placement | y=1..4 W1-GEMM head (+attn) | y=5 skip GEMM ==
__global__ void __launch_bounds__(256) mega1_kernel(
    const float* __restrict__ x, const float* __restrict__ W1,
    const float* __restrict__ Wskip,
    const float* __restrict__ asrc, const float* __restrict__ adst,
    const int* __restrict__ ei, int n, int E, int etot)
{
    __shared__ __half As[128 * 72];
    __shared__ __half Bs[64 * 72];
    int y = blockIdx.y;
    if (y == 0) {
        for (int e = blockIdx.x * blockDim.x + threadIdx.x; e < etot;
             e += gridDim.x * blockDim.x) {
            int s, d;
            if (e < E) { s = __ldg(ei + e); d = __ldg(ei + E + e); }
            else       { s = e - E;         d = s; }
            int pos = g_rowptr[d] + g_rank[e];
            g_csrc[pos] = s;
        }
    } else if (y <= 4) {
        gemm_body<true, true>(As, Bs, nullptr, x, W1, nullptr, g_h1h,
                              n, NFIN, NHC, y - 1, blockIdx.x, asrc, adst);
    } else {
        gemm_body<false, true>(As, Bs, nullptr, x, Wskip, g_skip, nullptr,
                               n, NFIN, NC, 0, blockIdx.x, nullptr, nullptr);
    }
}

// ===== layer-2 GEMM (fp16 A) =====
__global__ void __launch_bounds__(256) hgemm2_kernel(
    const __half* __restrict__ Ah, const float* __restrict__ Bf,
    int n, const float* __restrict__ asrc, const float* __restrict__ adst)
{
    __shared__ __half As[128 * 72];
    __shared__ __half Bs[64 * 72];
    gemm_body<true, false>(As, Bs, Ah, nullptr, Bf, nullptr, g_h1h,
                           n, NC, NHC, blockIdx.y, blockIdx.x, asrc, adst);
}

// == fused softmax + gather + BN-stats: warp per dst node, 8-wide pipeline ===
__global__ void __launch_bounds__(256) aggregate_kernel(
    int n, float* __restrict__ sums, float* __restrict__ sumsq)
{
    __shared__ float bsum[NC], bsq[NC];
    const int tid = threadIdx.x;
    if (tid < NC) { bsum[tid] = 0.f; bsq[tid] = 0.f; }
    __syncthreads();

    int w = (blockIdx.x * blockDim.x + tid) >> 5;
    int lane = tid & 31;
    const int h = lane >> 3;
    const int cb = (lane & 7) * 8;
    float a[8] = {0.f, 0.f, 0.f, 0.f, 0.f, 0.f, 0.f, 0.f};
    bool active = (w < n);

    if (active) {
        int beg = g_rowptr[w], end = g_rowptr[w + 1];
        float edv = g_ed[w * 4 + h];
        float s = 0.f;
        const __half* hb = g_h1h + h * 64 + cb;
        float a0 = 0.f, a1 = 0.f, a2 = 0.f, a3 = 0.f;
        float a4 = 0.f, a5 = 0.f, a6 = 0.f, a7 = 0.f;

        int pos = beg;
        for (; pos + 8 <= end; pos += 8) {
            int sv[8];
#pragma unroll
            for (int q = 0; q < 8; q++) sv[q] = g_csrc[pos + q];
            float ev[8];
            uint4 vv[8];
#pragma unroll
            for (int q = 0; q < 8; q++) {
                ev[q] = g_es[sv[q] * 4 + h] + edv;
                vv[q] = *(const uint4*)(hb + (size_t)sv[q] * NHC);
            }
#pragma unroll
            for (int q = 0; q < 8; q++) {
                float e = ev[q];
                e = e > 0.f ? e : 0.2f * e;
                float p = __expf(e);
                s += p;
                float2 f0 = __half22float2(*(__half2*)&vv[q].x);
                float2 f1 = __half22float2(*(__half2*)&vv[q].y);
                float2 f2 = __half22float2(*(__half2*)&vv[q].z);
                float2 f3 = __half22float2(*(__half2*)&vv[q].w);
                a0 += p * f0.x; a1 += p * f0.y; a2 += p * f1.x; a3 += p * f1.y;
                a4 += p * f2.x; a5 += p * f2.y; a6 += p * f3.x; a7 += p * f3.y;
            }
        }
        for (; pos < end; pos++) {
            int s0 = g_csrc[pos];
            float e0 = g_es[s0 * 4 + h] + edv;
            uint4 v0 = *(const uint4*)(hb + (size_t)s0 * NHC);
            e0 = e0 > 0.f ? e0 : 0.2f * e0;
            float p0 = __expf(e0);
            s += p0;
            float2 f0 = __half22float2(*(__half2*)&v0.x);
            float2 f1 = __half22float2(*(__half2*)&v0.y);
            float2 f2 = __half22float2(*(__half2*)&v0.z);
            float2 f3 = __half22float2(*(__half2*)&v0.w);
            a0 += p0 * f0.x; a1 += p0 * f0.y; a2 += p0 * f1.x; a3 += p0 * f1.y;
            a4 += p0 * f2.x; a5 += p0 * f2.y; a6 += p0 * f3.x; a7 += p0 * f3.y;
        }
        float inv = 0.25f / (s + 1e-16f);
        a[0] = a0 * inv; a[1] = a1 * inv; a[2] = a2 * inv; a[3] = a3 * inv;
        a[4] = a4 * inv; a[5] = a5 * inv; a[6] = a6 * inv; a[7] = a7 * inv;
    }
#pragma unroll
    for (int j = 0; j < 8; j++) {
        a[j] += __shfl_xor_sync(0xffffffffu, a[j], 8);
        a[j] += __shfl_xor_sync(0xffffffffu, a[j], 16);
    }
    if (active && lane < 8) {
        *(float4*)&g_acc[w * NC + lane * 8]     = make_float4(a[0], a[1], a[2], a[3]);
        *(float4*)&g_acc[w * NC + lane * 8 + 4] = make_float4(a[4], a[5], a[6], a[7]);
#pragma unroll
        for (int j = 0; j < 8; j++) {
            atomicAdd(&bsum[lane * 8 + j], a[j]);
            atomicAdd(&bsq[lane * 8 + j], a[j] * a[j]);
        }
    }
    __syncthreads();
    if (tid < NC) {
        atomicAdd(&sums[tid], bsum[tid]);
        atomicAdd(&sumsq[tid], bsq[tid]);
    }
}

// ===== fused epilogue 1 (BN finalize inline), float4-vectorized =====
// GAT bias b1/b2 cancels inside BatchNorm (additive constant) -> never applied.
__global__ void fuse1_kernel(const float* __restrict__ bskip,
                             const float* __restrict__ gamma,
                             const float* __restrict__ beta,
                             const float* __restrict__ sums,
                             const float* __restrict__ sumsq,
                             float ninv, int total4)
{
    int i = blockIdx.x * blockDim.x + threadIdx.x;
    if (i >= total4) return;
    int c4 = (i & 15) * 4;
    float4 sm = *(const float4*)&sums[c4];
    float4 sq = *(const float4*)&sumsq[c4];
    float4 gm = *(const float4*)&gamma[c4];
    float4 bt = *(const float4*)&beta[c4];
    float4 bk = *(const float4*)&bskip[c4];
    float4 av = ((const float4*)g_acc)[i];
    float4 sk = ((const float4*)g_skip)[i];
    float mu, var, sc, sh, x;
    float r[4];
    mu = sm.x * ninv; var = sq.x * ninv - mu * mu;
    sc = gm.x * rsqrtf(var + BN_EPS); sh = bt.x - mu * sc;
    x = av.x * sc + sh + sk.x + bk.x; r[0] = gelu_exact(x);
    mu = sm.y * ninv; var = sq.y * ninv - mu * mu;
    sc = gm.y * rsqrtf(var + BN_EPS); sh = bt.y - mu * sc;
    x = av.y * sc + sh + sk.y + bk.y; r[1] = gelu_exact(x);
    mu = sm.z * ninv; var = sq.z * ninv - mu * mu;
    sc = gm.z * rsqrtf(var + BN_EPS); sh = bt.z - mu * sc;
    x = av.z * sc + sh + sk.z + bk.z; r[2] = gelu_exact(x);
    mu = sm.w * ninv; var = sq.w * ninv - mu * mu;
    sc = gm.w * rsqrtf(var + BN_EPS); sh = bt.w - mu * sc;
    x = av.w * sc + sh + sk.w + bk.w; r[3] = gelu_exact(x);
    __half2 h0 = __floats2half2_rn(r[0], r[1]);
    __half2 h1 = __floats2half2_rn(r[2], r[3]);
    ((uint2*)g_hmidh)[i] = make_uint2(*(unsigned*)&h0, *(unsigned*)&h1);
}

// ===== fused epilogue 2 + pool; tail re-zeros cnt & stats for next call =====
__device__ __forceinline__ int lower_bound_dev(const int* arr, int n, int target) {
    int lo = 0, hi = n;
    while (lo < hi) {
        int mid = (lo + hi) >> 1;
        if (arr[mid] < target) lo = mid + 1; else hi = mid;
    }
    return lo;
}

__global__ void fuse2_pool_kernel(const int* __restrict__ batch,
                                  const float* __restrict__ gamma,
                                  const float* __restrict__ beta,
                                  const float* __restrict__ sums,
                                  const float* __restrict__ sumsq,
                                  float ninv,
                                  float* __restrict__ out, int n)
{
    int g = blockIdx.x;
    __shared__ int bounds[2];
    if (threadIdx.x < 2)
        bounds[threadIdx.x] = lower_bound_dev(batch, n, g + threadIdx.x);
    __syncthreads();
    int lo = bounds[0], hi = bounds[1];
    int c = threadIdx.x & 63, rq = threadIdx.x >> 6;
    float mu = sums[c] * ninv;
    float var = sumsq[c] * ninv - mu * mu;
    float sc = gamma[c] * rsqrtf(var + BN_EPS);
    float sh = beta[c] - mu * sc;
    float s = 0.f;
    for (int node = lo + rq; node < hi; node += 4) {
        float res = __half2float(g_hmidh[node * NC + c]);
        float x = g_acc[node * NC + c] * sc + sh + res;
        s += gelu_exact(x);
    }
    __shared__ float red[256];
    red[threadIdx.x] = s;
    __syncthreads();
    if (threadIdx.x < 64) {
        float tot = red[c] + red[c + 64] + red[c + 128] + red[c + 192];
        out[g * NC + c] = tot / fmaxf((float)(hi - lo), 1.f);
    }
    for (int i = blockIdx.x * blockDim.x + threadIdx.x; i < n;
         i += gridDim.x * blockDim.x)
        g_cnt[i] = 0;
    if (blockIdx.x == 0 && threadIdx.x < 4 * NC)
        g_bnstats[threadIdx.x] = 0.f;
}

// ================= launch =================
extern "C" void kernel_launch(void* const* d_in, const int* in_sizes, int n_in,
                              void* d_out, int out_size) {
    const float* x      = (const float*)d_in[0];
    const float* W1     = (const float*)d_in[1];
    const float* a_src1 = (const float*)d_in[2];
    const float* a_dst1 = (const float*)d_in[3];
    const float* Wskip  = (const float*)d_in[5];
    const float* bskip  = (const float*)d_in[6];
    const float* g1     = (const float*)d_in[7];
    const float* be1    = (const float*)d_in[8];
    const float* W2     = (const float*)d_in[9];
    const float* a_src2 = (const float*)d_in[10];
    const float* a_dst2 = (const float*)d_in[11];
    const float* g2     = (const float*)d_in[13];
    const float* be2    = (const float*)d_in[14];
    const int*   ei     = (const int*)d_in[15];
    const int*   batch  = (const int*)d_in[16];
    float* out = (float*)d_out;

    int n = in_sizes[0] / NFIN;
    int E = in_sizes[15] / 2;
    int etot = E + n;
    float ninv = 1.f / (float)n;

    float* p_stats;
    cudaGetSymbolAddress((void**)&p_stats, g_bnstats);
    float* p_sums0  = p_stats;
    float* p_sumsq0 = p_stats + NC;
    float* p_sums1  = p_stats + 2 * NC;
    float* p_sumsq1 = p_stats + 3 * NC;
    __half* p_hmidh;
    cudaGetSymbolAddress((void**)&p_hmidh, g_hmidh);

    int gx = (n + 127) / 128;
    int ab = (n * 32 + 255) / 256;
    int hb = (etot + 2047) / 2048;
    int f4 = n * NC / 4;
    int fb4 = (f4 + 255) / 256;

    hist_scan_kernel<<<hb, 1024>>>(ei, E, etot, n, hb);

    mega1_kernel<<<dim3(gx, 6), 256>>>(x, W1, Wskip, a_src1, a_dst1, ei, n, E, etot);

    aggregate_kernel<<<ab, 256>>>(n, p_sums0, p_sumsq0);
    fuse1_kernel<<<fb4, 256>>>(bskip, g1, be1, p_sums0, p_sumsq0, ninv, f4);

    hgemm2_kernel<<<dim3(gx, 4), 256>>>(p_hmidh, W2, n, a_src2, a_dst2);
    aggregate_kernel<<<ab, 256>>>(n, p_sums1, p_sumsq1);
    fuse2_pool_kernel<<<N_GRAPH, 256>>>(batch, g2, be2, p_sums1, p_sumsq1, ninv, out, n);
}